// round 13
// baseline (speedup 1.0000x reference)
#include <cuda_runtime.h>
#include <cuda_fp16.h>
#include <math.h>

#define N_NODES 50000
#define N_EDGES 800000
#define NBLK    ((N_NODES + 255) / 256)

// ---------------- scratch ----------------
__device__ int      g_idx64;
__device__ unsigned g_bcount = 0;
__device__ int      g_deg[N_NODES];
__device__ float    g_invdeg[N_NODES];
__device__ int      g_rowptr[N_NODES + 1];
__device__ int      g_cursor[N_NODES];
__device__ int      g_src[N_EDGES];
__device__ int      g_bsum[256];
__device__ int      g_boff[256];
// fp16 activation planes
__device__ __half g_xh [(size_t)N_NODES * 128];
__device__ __half g_hah[(size_t)N_NODES * 128];
__device__ __half g_hbh[(size_t)N_NODES * 128];
// fp16 weights: [Wl1|Wr1|Wl2|Wr2|Wl3|Wr3|Wl4|Wr4]
__device__ __half g_w16[90112];

// ---------------- helpers ----------------
__device__ __forceinline__ void mma16816(float* d, const unsigned* a, const unsigned* b) {
    asm volatile(
        "mma.sync.aligned.m16n8k16.row.col.f32.f16.f16.f32 "
        "{%0,%1,%2,%3},{%4,%5,%6,%7},{%8,%9},{%0,%1,%2,%3};"
        : "+f"(d[0]), "+f"(d[1]), "+f"(d[2]), "+f"(d[3])
        : "r"(a[0]), "r"(a[1]), "r"(a[2]), "r"(a[3]), "r"(b[0]), "r"(b[1]));
}

__device__ __forceinline__ int clampi(int v, int lo, int hi) {
    return v < lo ? lo : (v > hi ? hi : v);
}

// ---------------- merged preprocessing: zero + detect + wsplit + xsplit ----------------
__global__ void k_pre(const unsigned int* __restrict__ w, const float* __restrict__ x,
                      const float* Wl1, const float* Wr1, const float* Wl2, const float* Wr2,
                      const float* Wl3, const float* Wr3, const float* Wl4, const float* Wr4) {
    int i = blockIdx.x * 256 + threadIdx.x;
    if (i < N_NODES) g_deg[i] = 0;
    if (blockIdx.x == 0 && threadIdx.x < 32) {
        int lane = threadIdx.x;
        unsigned int v = w[2 * lane + 1] | w[2 * (lane + 32) + 1] |
                         w[2 * (lane + 64) + 1] | w[2 * (lane + 96) + 1];
        unsigned int any = __ballot_sync(0xffffffffu, v != 0u);
        if (lane == 0) g_idx64 = (any == 0u) ? 1 : 0;
    }
    if (i < N_NODES * 128)
        g_xh[i] = __float2half_rn(x[i]);
    {
        const float* src[8] = {Wl1, Wr1, Wl2, Wr2, Wl3, Wr3, Wl4, Wr4};
        const int cnt[8] = {16384, 16384, 16384, 16384, 8192, 8192, 4096, 4096};
        const int dh[8]  = {0, 16384, 32768, 49152, 65536, 73728, 81920, 86016};
        #pragma unroll
        for (int s = 0; s < 8; s++)
            if (i < cnt[s])
                g_w16[dh[s] + i] = __float2half_rn(src[s][i]);
    }
}

// ---------------- CSR build (4 edges/thread, vectorized loads) ----------------
__global__ void k_count(const void* __restrict__ ei) {
    int i = blockIdx.x * blockDim.x + threadIdx.x;
    if (i * 4 >= N_EDGES) return;
    int d[4];
    if (g_idx64) {
        const ulonglong2* p = (const ulonglong2*)((const long long*)ei + N_EDGES);
        ulonglong2 a = p[i * 2], b = p[i * 2 + 1];
        d[0] = (int)a.x; d[1] = (int)a.y; d[2] = (int)b.x; d[3] = (int)b.y;
    } else {
        int4 v = ((const int4*)((const int*)ei + N_EDGES))[i];
        d[0] = v.x; d[1] = v.y; d[2] = v.z; d[3] = v.w;
    }
    #pragma unroll
    for (int j = 0; j < 4; j++)
        atomicAdd(&g_deg[clampi(d[j], 0, N_NODES - 1)], 1);
}

__global__ void k_bsumscan() {
    __shared__ int sh[256];
    __shared__ bool last;
    int i = blockIdx.x * 256 + threadIdx.x;
    sh[threadIdx.x] = (i < N_NODES) ? g_deg[i] : 0;
    __syncthreads();
    for (int off = 128; off > 0; off >>= 1) {
        if (threadIdx.x < off) sh[threadIdx.x] += sh[threadIdx.x + off];
        __syncthreads();
    }
    if (threadIdx.x == 0) {
        g_bsum[blockIdx.x] = sh[0];
        __threadfence();
        unsigned v = atomicAdd(&g_bcount, 1u);
        last = (v == gridDim.x - 1);
    }
    __syncthreads();
    if (last) {
        __threadfence();
        int t = threadIdx.x;
        int v = (t < NBLK) ? g_bsum[t] : 0;
        sh[t] = v;
        __syncthreads();
        for (int off = 1; off < 256; off <<= 1) {
            int u = (t >= off) ? sh[t - off] : 0;
            __syncthreads();
            sh[t] += u;
            __syncthreads();
        }
        if (t < NBLK) g_boff[t] = sh[t] - v;
        if (t == 0) { g_rowptr[N_NODES] = N_EDGES; g_bcount = 0; }
    }
}

__global__ void k_scatter() {
    __shared__ int sh[256];
    int t = threadIdx.x;
    int i = blockIdx.x * 256 + t;
    int d = (i < N_NODES) ? g_deg[i] : 0;
    sh[t] = d;
    __syncthreads();
    for (int off = 1; off < 256; off <<= 1) {
        int u = (t >= off) ? sh[t - off] : 0;
        __syncthreads();
        sh[t] += u;
        __syncthreads();
    }
    if (i < N_NODES) {
        int base = g_boff[blockIdx.x] + sh[t] - d;
        g_rowptr[i] = base;
        g_cursor[i] = base;
        g_invdeg[i] = 1.0f / fmaxf((float)d, 1.0f);
    }
}

__global__ void k_fill(const void* __restrict__ ei) {
    int i = blockIdx.x * blockDim.x + threadIdx.x;
    if (i * 4 >= N_EDGES) return;
    int s[4], d[4];
    if (g_idx64) {
        const ulonglong2* ps = (const ulonglong2*)ei;
        const ulonglong2* pd = (const ulonglong2*)((const long long*)ei + N_EDGES);
        ulonglong2 sa = ps[i * 2], sb = ps[i * 2 + 1];
        ulonglong2 da = pd[i * 2], db = pd[i * 2 + 1];
        s[0] = (int)sa.x; s[1] = (int)sa.y; s[2] = (int)sb.x; s[3] = (int)sb.y;
        d[0] = (int)da.x; d[1] = (int)da.y; d[2] = (int)db.x; d[3] = (int)db.y;
    } else {
        int4 sv = ((const int4*)ei)[i];
        int4 dv = ((const int4*)((const int*)ei + N_EDGES))[i];
        s[0] = sv.x; s[1] = sv.y; s[2] = sv.z; s[3] = sv.w;
        d[0] = dv.x; d[1] = dv.y; d[2] = dv.z; d[3] = dv.w;
    }
    #pragma unroll
    for (int j = 0; j < 4; j++) {
        int pos = atomicAdd(&g_cursor[clampi(d[j], 0, N_NODES - 1)], 1);
        pos = clampi(pos, 0, N_EDGES - 1);
        g_src[pos] = clampi(s[j], 0, N_NODES - 1);
    }
}

// ---------------- fused SAGE layer: tile-local aggregation + HMMA + epilogue ----------------
// Phase 1: 8 warps aggregate the block's 128 nodes (fp16 gather, fp32 acc),
//          writing results straight into the MMA A-panel smem layout.
// Phase 2: per 64-K-offset: stage self-x panel + Wl/Wr panels; mma(agg,Wl); mma(x,Wr).
// XSEL: 0 = g_xh, 1 = g_hah, 2 = g_hbh (gather source AND self input).
// OSEL: 0 = dout, 1 = g_hah, 2 = g_hbh.
template <int CIN, int COUT, bool RELU, bool LSM, int XSEL, int OSEL, int WBASE>
__launch_bounds__(256, 1)
__global__ void k_layer(const float* __restrict__ bl, float* __restrict__ dout) {
    constexpr int PPS = CIN / 64;                // A-panels per row-block
    constexpr int CC  = COUT * CIN;
    constexpr int RT  = (COUT == 128) ? 2 : 1;

    extern __shared__ unsigned smemW[];
    unsigned* AsAggW = smemW;                    // PPS * 128 * 36 words
    unsigned* AsW    = AsAggW + PPS * 4608;      // 128 * 36
    unsigned* Bs0W   = AsW + 4608;               // COUT * 36
    unsigned* Bs1W   = Bs0W + COUT * 36;         // COUT * 36

    const __half* feat = (XSEL == 0) ? g_xh : (XSEL == 1) ? g_hah : g_hbh;

    const int tid = threadIdx.x, warp = tid >> 5, lane = tid & 31;
    const int g = lane >> 2, t = lane & 3;
    const int nb = blockIdx.x * 128;
    const int rowbase = (COUT == 128) ? (warp >> 1) * 32 : warp * 16;
    const int colbase = (COUT == 128) ? (warp & 1) * 64 : 0;

    // ---- phase 1: aggregate 16 nodes per warp into AsAgg panels ----
    if (CIN == 128) {
        const uint2* f = (const uint2*)feat;
        #pragma unroll 1
        for (int i = 0; i < 16; i++) {
            int row = warp * 16 + i;
            int n = nb + row; if (n >= N_NODES) n = N_NODES - 1;
            int beg = g_rowptr[n], end = g_rowptr[n + 1];
            float a0 = 0.f, a1 = 0.f, a2 = 0.f, a3 = 0.f;
            int e = beg;
            for (; e + 1 < end; e += 2) {
                int s0 = g_src[e], s1 = g_src[e + 1];
                uint2 r0 = f[(size_t)s0 * 32 + lane];
                uint2 r1 = f[(size_t)s1 * 32 + lane];
                float2 p0 = __half22float2(*(__half2*)&r0.x);
                float2 p1 = __half22float2(*(__half2*)&r0.y);
                float2 q0 = __half22float2(*(__half2*)&r1.x);
                float2 q1 = __half22float2(*(__half2*)&r1.y);
                a0 += p0.x + q0.x; a1 += p0.y + q0.y;
                a2 += p1.x + q1.x; a3 += p1.y + q1.y;
            }
            if (e < end) {
                uint2 r0 = f[(size_t)g_src[e] * 32 + lane];
                float2 p0 = __half22float2(*(__half2*)&r0.x);
                float2 p1 = __half22float2(*(__half2*)&r0.y);
                a0 += p0.x; a1 += p0.y; a2 += p1.x; a3 += p1.y;
            }
            float iv = g_invdeg[n];
            __half2 h0 = __floats2half2_rn(a0 * iv, a1 * iv);
            __half2 h1 = __floats2half2_rn(a2 * iv, a3 * iv);
            // lane owns channels [lane*4, lane*4+4): panel = lane/16, words (lane%16)*2, +1
            unsigned* dst = AsAggW + (lane >> 4) * 4608 + row * 36 + (lane & 15) * 2;
            uint2 wv;
            wv.x = *(unsigned*)&h0;
            wv.y = *(unsigned*)&h1;
            *(uint2*)dst = wv;
        }
    } else { // CIN == 64: lane owns 2 channels -> 1 word at row*36 + lane
        const unsigned* f = (const unsigned*)feat;
        #pragma unroll 1
        for (int i = 0; i < 16; i++) {
            int row = warp * 16 + i;
            int n = nb + row; if (n >= N_NODES) n = N_NODES - 1;
            int beg = g_rowptr[n], end = g_rowptr[n + 1];
            float a0 = 0.f, a1 = 0.f;
            int e = beg;
            for (; e + 1 < end; e += 2) {
                int s0 = g_src[e], s1 = g_src[e + 1];
                float2 p = __half22float2(*(__half2*)&f[(size_t)s0 * 32 + lane]);
                float2 q = __half22float2(*(__half2*)&f[(size_t)s1 * 32 + lane]);
                a0 += p.x + q.x; a1 += p.y + q.y;
            }
            if (e < end) {
                float2 p = __half22float2(*(__half2*)&f[(size_t)g_src[e] * 32 + lane]);
                a0 += p.x; a1 += p.y;
            }
            float iv = g_invdeg[n];
            __half2 h0 = __floats2half2_rn(a0 * iv, a1 * iv);
            AsAggW[row * 36 + lane] = *(unsigned*)&h0;
        }
    }
    __syncthreads();

    // ---- phase 2: MMA ----
    float acc[RT][8][4];
    #pragma unroll
    for (int rt = 0; rt < RT; rt++)
        #pragma unroll
        for (int f = 0; f < 8; f++)
            #pragma unroll
            for (int j = 0; j < 4; j++) acc[rt][f][j] = 0.f;

    auto domma = [&](const unsigned* AW, const unsigned* BW) {
        #pragma unroll
        for (int kc = 0; kc < 4; kc++) {
            unsigned a[RT][4];
            #pragma unroll
            for (int rt = 0; rt < RT; rt++) {
                int r0 = rowbase + rt * 16 + g;
                a[rt][0] = AW[r0 * 36 + kc * 8 + t];
                a[rt][1] = AW[(r0 + 8) * 36 + kc * 8 + t];
                a[rt][2] = AW[r0 * 36 + kc * 8 + t + 4];
                a[rt][3] = AW[(r0 + 8) * 36 + kc * 8 + t + 4];
            }
            unsigned b[8][2];
            #pragma unroll
            for (int f = 0; f < 8; f++) {
                int br = colbase + f * 8 + g;
                b[f][0] = BW[br * 36 + kc * 8 + t];
                b[f][1] = BW[br * 36 + kc * 8 + t + 4];
            }
            #pragma unroll
            for (int rt = 0; rt < RT; rt++)
                #pragma unroll
                for (int f = 0; f < 8; f++)
                    mma16816(acc[rt][f], a[rt], b[f]);
        }
    };

    #pragma unroll
    for (int off4 = 0; off4 < PPS; off4++) {
        const int off = off4 * 64;
        if (off4 > 0) __syncthreads();   // protect As/Bs reuse
        // stage self-x panel + both weight panels for this K-offset
        #pragma unroll
        for (int it = 0; it < 4; it++) {
            int idx = tid + it * 256;
            int row = idx >> 3, q = idx & 7;
            int n = nb + row; if (n >= N_NODES) n = N_NODES - 1;
            ((uint4*)AsW)[row * 9 + q] =
                ((const uint4*)feat)[(size_t)n * (CIN / 8) + off / 8 + q];
        }
        #pragma unroll
        for (int it = 0; it < COUT / 32; it++) {
            int idx = tid + it * 256;
            int row = idx >> 3, q = idx & 7;
            int woff = row * CIN + off;
            ((uint4*)Bs0W)[row * 9 + q] = ((const uint4*)g_w16)[(WBASE + woff) / 8 + q];
            ((uint4*)Bs1W)[row * 9 + q] = ((const uint4*)g_w16)[(WBASE + CC + woff) / 8 + q];
        }
        __syncthreads();
        domma(AsAggW + off4 * 4608, Bs0W);   // agg @ Wl
        domma(AsW, Bs1W);                    // x   @ Wr
    }

    // ---- epilogue ----
    if (!LSM) {
        __half* oh = (OSEL == 1) ? g_hah : g_hbh;
        #pragma unroll
        for (int rt = 0; rt < RT; rt++) {
            int n0 = nb + rowbase + rt * 16 + g;
            int n1 = n0 + 8;
            #pragma unroll
            for (int f = 0; f < 8; f++) {
                int col = colbase + f * 8 + 2 * t;
                float2 bb = *(const float2*)&bl[col];
                float v0 = acc[rt][f][0] + bb.x, v1 = acc[rt][f][1] + bb.y;
                float v2 = acc[rt][f][2] + bb.x, v3 = acc[rt][f][3] + bb.y;
                if (RELU) {
                    v0 = fmaxf(v0, 0.f); v1 = fmaxf(v1, 0.f);
                    v2 = fmaxf(v2, 0.f); v3 = fmaxf(v3, 0.f);
                }
                if (n0 < N_NODES)
                    *(__half2*)&oh[(size_t)n0 * COUT + col] = __floats2half2_rn(v0, v1);
                if (n1 < N_NODES)
                    *(__half2*)&oh[(size_t)n1 * COUT + col] = __floats2half2_rn(v2, v3);
            }
        }
    } else {
        float v0[8], v1[8], w0[8], w1[8];
        float mxA = -1e30f, mxB = -1e30f;
        #pragma unroll
        for (int f = 0; f < 8; f++) {
            int col = f * 8 + 2 * t;
            float2 bb = *(const float2*)&bl[col];
            v0[f] = acc[0][f][0] + bb.x; v1[f] = acc[0][f][1] + bb.y;
            w0[f] = acc[0][f][2] + bb.x; w1[f] = acc[0][f][3] + bb.y;
            mxA = fmaxf(mxA, fmaxf(v0[f], v1[f]));
            mxB = fmaxf(mxB, fmaxf(w0[f], w1[f]));
        }
        #pragma unroll
        for (int m = 1; m < 4; m <<= 1) {
            mxA = fmaxf(mxA, __shfl_xor_sync(0xffffffffu, mxA, m));
            mxB = fmaxf(mxB, __shfl_xor_sync(0xffffffffu, mxB, m));
        }
        float sA = 0.f, sB = 0.f;
        #pragma unroll
        for (int f = 0; f < 8; f++) {
            sA += expf(v0[f] - mxA) + expf(v1[f] - mxA);
            sB += expf(w0[f] - mxB) + expf(w1[f] - mxB);
        }
        #pragma unroll
        for (int m = 1; m < 4; m <<= 1) {
            sA += __shfl_xor_sync(0xffffffffu, sA, m);
            sB += __shfl_xor_sync(0xffffffffu, sB, m);
        }
        float lA = mxA + logf(sA), lB = mxB + logf(sB);
        int n0 = nb + rowbase + g;
        int n1 = n0 + 8;
        if (n0 < N_NODES) {
            #pragma unroll
            for (int f = 0; f < 8; f++)
                *(float2*)&dout[(size_t)n0 * 64 + f * 8 + 2 * t] =
                    make_float2(v0[f] - lA, v1[f] - lA);
        }
        if (n1 < N_NODES) {
            #pragma unroll
            for (int f = 0; f < 8; f++)
                *(float2*)&dout[(size_t)n1 * 64 + f * 8 + 2 * t] =
                    make_float2(w0[f] - lB, w1[f] - lB);
        }
    }
}

// ---------------- launch ----------------
extern "C" void kernel_launch(void* const* d_in, const int* in_sizes, int n_in,
                              void* d_out, int out_size) {
    (void)in_sizes; (void)n_in; (void)out_size;
    const float* x   = (const float*)d_in[0];
    const void*  ei  = d_in[1];
    const float* Wl1 = (const float*)d_in[2];
    const float* bl1 = (const float*)d_in[3];
    const float* Wr1 = (const float*)d_in[4];
    const float* Wl2 = (const float*)d_in[5];
    const float* bl2 = (const float*)d_in[6];
    const float* Wr2 = (const float*)d_in[7];
    const float* Wl3 = (const float*)d_in[8];
    const float* bl3 = (const float*)d_in[9];
    const float* Wr3 = (const float*)d_in[10];
    const float* Wl4 = (const float*)d_in[11];
    const float* bl4 = (const float*)d_in[12];
    const float* Wr4 = (const float*)d_in[13];
    float* out = (float*)d_out;

    // dynamic smem: (PPS*4608 + 4608 + 2*COUT*36) words * 4B
    const int SMEM12 = (2 * 4608 + 4608 + 2 * 128 * 36) * 4;  // 92160
    const int SMEM3  = (2 * 4608 + 4608 + 2 * 64 * 36) * 4;   // 73728
    const int SMEM4  = (1 * 4608 + 4608 + 2 * 64 * 36) * 4;   // 55296
    cudaFuncSetAttribute(k_layer<128,128,true ,false,0,1,0    >, cudaFuncAttributeMaxDynamicSharedMemorySize, SMEM12);
    cudaFuncSetAttribute(k_layer<128,128,true ,false,1,2,32768>, cudaFuncAttributeMaxDynamicSharedMemorySize, SMEM12);
    cudaFuncSetAttribute(k_layer<128,64 ,true ,false,2,1,65536>, cudaFuncAttributeMaxDynamicSharedMemorySize, SMEM3);
    cudaFuncSetAttribute(k_layer<64 ,64 ,false,true ,1,0,81920>, cudaFuncAttributeMaxDynamicSharedMemorySize, SMEM4);

    // preprocessing + CSR build
    k_pre<<<(N_NODES * 128 + 255) / 256, 256>>>((const unsigned int*)ei, x,
                                                Wl1, Wr1, Wl2, Wr2, Wl3, Wr3, Wl4, Wr4);
    k_count<<<(N_EDGES / 4 + 255) / 256, 256>>>(ei);
    k_bsumscan<<<NBLK, 256>>>();
    k_scatter<<<NBLK, 256>>>();
    k_fill<<<(N_EDGES / 4 + 255) / 256, 256>>>(ei);

    const int GM = (N_NODES + 127) / 128;   // 391 blocks

    // fused layers
    k_layer<128, 128, true, false, 0, 1, 0    ><<<GM, 256, SMEM12>>>(bl1, nullptr);
    k_layer<128, 128, true, false, 1, 2, 32768><<<GM, 256, SMEM12>>>(bl2, nullptr);
    k_layer<128, 64,  true, false, 2, 1, 65536><<<GM, 256, SMEM3 >>>(bl3, nullptr);
    k_layer<64,  64,  false, true, 1, 0, 81920><<<GM, 256, SMEM4 >>>(bl4, out);
}

// round 14
// speedup vs baseline: 1.8236x; 1.8236x over previous
#include <cuda_runtime.h>
#include <cuda_fp16.h>
#include <math.h>

#define N_NODES 50000
#define N_EDGES 800000
#define NBLK    ((N_NODES + 255) / 256)

// ---------------- scratch ----------------
__device__ int      g_idx64;
__device__ unsigned g_bcount = 0;
__device__ int      g_deg[N_NODES];
__device__ float    g_invdeg[N_NODES];
__device__ int      g_rowptr[N_NODES + 1];
__device__ int      g_cursor[N_NODES];
__device__ int      g_src[N_EDGES];
__device__ int      g_bsum[256];
__device__ int      g_boff[256];
// fp16 activation planes (pure fp16 operands, fp32 accumulate in MMA)
__device__ __half g_xh  [(size_t)N_NODES * 128];
__device__ __half g_aggh[(size_t)N_NODES * 128];
__device__ __half g_hah [(size_t)N_NODES * 128];
__device__ __half g_hbh [(size_t)N_NODES * 128];
// fp16 weights: [Wl1|Wr1|Wl2|Wr2|Wl3|Wr3|Wl4|Wr4]
__device__ __half g_w16[90112];

// ---------------- helpers ----------------
__device__ __forceinline__ void mma16816(float* d, const unsigned* a, const unsigned* b) {
    asm volatile(
        "mma.sync.aligned.m16n8k16.row.col.f32.f16.f16.f32 "
        "{%0,%1,%2,%3},{%4,%5,%6,%7},{%8,%9},{%0,%1,%2,%3};"
        : "+f"(d[0]), "+f"(d[1]), "+f"(d[2]), "+f"(d[3])
        : "r"(a[0]), "r"(a[1]), "r"(a[2]), "r"(a[3]), "r"(b[0]), "r"(b[1]));
}

__device__ __forceinline__ int clampi(int v, int lo, int hi) {
    return v < lo ? lo : (v > hi ? hi : v);
}

// ---------------- merged preprocessing: zero + detect + wsplit + xsplit ----------------
__global__ void k_pre(const unsigned int* __restrict__ w, const float* __restrict__ x,
                      const float* Wl1, const float* Wr1, const float* Wl2, const float* Wr2,
                      const float* Wl3, const float* Wr3, const float* Wl4, const float* Wr4) {
    int i = blockIdx.x * 256 + threadIdx.x;
    if (i < N_NODES) g_deg[i] = 0;
    if (blockIdx.x == 0 && threadIdx.x < 32) {
        int lane = threadIdx.x;
        unsigned int v = w[2 * lane + 1] | w[2 * (lane + 32) + 1] |
                         w[2 * (lane + 64) + 1] | w[2 * (lane + 96) + 1];
        unsigned int any = __ballot_sync(0xffffffffu, v != 0u);
        if (lane == 0) g_idx64 = (any == 0u) ? 1 : 0;
    }
    if (i < N_NODES * 128)
        g_xh[i] = __float2half_rn(x[i]);
    {
        const float* src[8] = {Wl1, Wr1, Wl2, Wr2, Wl3, Wr3, Wl4, Wr4};
        const int cnt[8] = {16384, 16384, 16384, 16384, 8192, 8192, 4096, 4096};
        const int dh[8]  = {0, 16384, 32768, 49152, 65536, 73728, 81920, 86016};
        #pragma unroll
        for (int s = 0; s < 8; s++)
            if (i < cnt[s])
                g_w16[dh[s] + i] = __float2half_rn(src[s][i]);
    }
}

// ---------------- CSR build (4 edges/thread, vectorized loads) ----------------
__global__ void k_count(const void* __restrict__ ei) {
    int i = blockIdx.x * blockDim.x + threadIdx.x;
    if (i * 4 >= N_EDGES) return;
    int d[4];
    if (g_idx64) {
        const ulonglong2* p = (const ulonglong2*)((const long long*)ei + N_EDGES);
        ulonglong2 a = p[i * 2], b = p[i * 2 + 1];
        d[0] = (int)a.x; d[1] = (int)a.y; d[2] = (int)b.x; d[3] = (int)b.y;
    } else {
        int4 v = ((const int4*)((const int*)ei + N_EDGES))[i];
        d[0] = v.x; d[1] = v.y; d[2] = v.z; d[3] = v.w;
    }
    #pragma unroll
    for (int j = 0; j < 4; j++)
        atomicAdd(&g_deg[clampi(d[j], 0, N_NODES - 1)], 1);
}

__global__ void k_bsumscan() {
    __shared__ int sh[256];
    __shared__ bool last;
    int i = blockIdx.x * 256 + threadIdx.x;
    sh[threadIdx.x] = (i < N_NODES) ? g_deg[i] : 0;
    __syncthreads();
    for (int off = 128; off > 0; off >>= 1) {
        if (threadIdx.x < off) sh[threadIdx.x] += sh[threadIdx.x + off];
        __syncthreads();
    }
    if (threadIdx.x == 0) {
        g_bsum[blockIdx.x] = sh[0];
        __threadfence();
        unsigned v = atomicAdd(&g_bcount, 1u);
        last = (v == gridDim.x - 1);
    }
    __syncthreads();
    if (last) {
        __threadfence();
        int t = threadIdx.x;
        int v = (t < NBLK) ? g_bsum[t] : 0;
        sh[t] = v;
        __syncthreads();
        for (int off = 1; off < 256; off <<= 1) {
            int u = (t >= off) ? sh[t - off] : 0;
            __syncthreads();
            sh[t] += u;
            __syncthreads();
        }
        if (t < NBLK) g_boff[t] = sh[t] - v;
        if (t == 0) { g_rowptr[N_NODES] = N_EDGES; g_bcount = 0; }
    }
}

__global__ void k_scatter() {
    __shared__ int sh[256];
    int t = threadIdx.x;
    int i = blockIdx.x * 256 + t;
    int d = (i < N_NODES) ? g_deg[i] : 0;
    sh[t] = d;
    __syncthreads();
    for (int off = 1; off < 256; off <<= 1) {
        int u = (t >= off) ? sh[t - off] : 0;
        __syncthreads();
        sh[t] += u;
        __syncthreads();
    }
    if (i < N_NODES) {
        int base = g_boff[blockIdx.x] + sh[t] - d;
        g_rowptr[i] = base;
        g_cursor[i] = base;
        g_invdeg[i] = 1.0f / fmaxf((float)d, 1.0f);
    }
}

__global__ void k_fill(const void* __restrict__ ei) {
    int i = blockIdx.x * blockDim.x + threadIdx.x;
    if (i * 4 >= N_EDGES) return;
    int s[4], d[4];
    if (g_idx64) {
        const ulonglong2* ps = (const ulonglong2*)ei;
        const ulonglong2* pd = (const ulonglong2*)((const long long*)ei + N_EDGES);
        ulonglong2 sa = ps[i * 2], sb = ps[i * 2 + 1];
        ulonglong2 da = pd[i * 2], db = pd[i * 2 + 1];
        s[0] = (int)sa.x; s[1] = (int)sa.y; s[2] = (int)sb.x; s[3] = (int)sb.y;
        d[0] = (int)da.x; d[1] = (int)da.y; d[2] = (int)db.x; d[3] = (int)db.y;
    } else {
        int4 sv = ((const int4*)ei)[i];
        int4 dv = ((const int4*)((const int*)ei + N_EDGES))[i];
        s[0] = sv.x; s[1] = sv.y; s[2] = sv.z; s[3] = sv.w;
        d[0] = dv.x; d[1] = dv.y; d[2] = dv.z; d[3] = dv.w;
    }
    #pragma unroll
    for (int j = 0; j < 4; j++) {
        int pos = atomicAdd(&g_cursor[clampi(d[j], 0, N_NODES - 1)], 1);
        pos = clampi(pos, 0, N_EDGES - 1);
        g_src[pos] = clampi(s[j], 0, N_NODES - 1);
    }
}

// ---------------- mean aggregation: fp16 gathers (MLP 4), fp32 accumulate, fp16 out --------
// SSEL: 0 = g_xh, 1 = g_hah, 2 = g_hbh. Output: g_aggh (width C).
template <int C, int SSEL>
__global__ void k_agg() {
    const __half* feat = (SSEL == 0) ? g_xh : (SSEL == 1) ? g_hah : g_hbh;
    int w    = (blockIdx.x * blockDim.x + threadIdx.x) >> 5;
    int lane = threadIdx.x & 31;
    if (w >= N_NODES) return;
    int beg = g_rowptr[w], end = g_rowptr[w + 1];
    if (C == 128) {
        const uint2* f = (const uint2*)feat;
        float a0 = 0.f, a1 = 0.f, a2 = 0.f, a3 = 0.f;
        int e = beg;
        for (; e + 3 < end; e += 4) {
            int s0 = g_src[e],     s1 = g_src[e + 1];
            int s2 = g_src[e + 2], s3 = g_src[e + 3];
            uint2 r0 = f[(size_t)s0 * 32 + lane];
            uint2 r1 = f[(size_t)s1 * 32 + lane];
            uint2 r2 = f[(size_t)s2 * 32 + lane];
            uint2 r3 = f[(size_t)s3 * 32 + lane];
            float2 p0 = __half22float2(*(__half2*)&r0.x);
            float2 p1 = __half22float2(*(__half2*)&r0.y);
            float2 q0 = __half22float2(*(__half2*)&r1.x);
            float2 q1 = __half22float2(*(__half2*)&r1.y);
            float2 u0 = __half22float2(*(__half2*)&r2.x);
            float2 u1 = __half22float2(*(__half2*)&r2.y);
            float2 v0 = __half22float2(*(__half2*)&r3.x);
            float2 v1 = __half22float2(*(__half2*)&r3.y);
            a0 += (p0.x + q0.x) + (u0.x + v0.x);
            a1 += (p0.y + q0.y) + (u0.y + v0.y);
            a2 += (p1.x + q1.x) + (u1.x + v1.x);
            a3 += (p1.y + q1.y) + (u1.y + v1.y);
        }
        for (; e < end; e++) {
            uint2 r0 = f[(size_t)g_src[e] * 32 + lane];
            float2 p0 = __half22float2(*(__half2*)&r0.x);
            float2 p1 = __half22float2(*(__half2*)&r0.y);
            a0 += p0.x; a1 += p0.y; a2 += p1.x; a3 += p1.y;
        }
        float iv = g_invdeg[w];
        size_t base = (size_t)w * 128 + lane * 4;
        *(__half2*)&g_aggh[base]     = __floats2half2_rn(a0 * iv, a1 * iv);
        *(__half2*)&g_aggh[base + 2] = __floats2half2_rn(a2 * iv, a3 * iv);
    } else { // C == 64
        const unsigned* f = (const unsigned*)feat;
        float a0 = 0.f, a1 = 0.f;
        int e = beg;
        for (; e + 3 < end; e += 4) {
            int s0 = g_src[e],     s1 = g_src[e + 1];
            int s2 = g_src[e + 2], s3 = g_src[e + 3];
            float2 p = __half22float2(*(__half2*)&f[(size_t)s0 * 32 + lane]);
            float2 q = __half22float2(*(__half2*)&f[(size_t)s1 * 32 + lane]);
            float2 u = __half22float2(*(__half2*)&f[(size_t)s2 * 32 + lane]);
            float2 v = __half22float2(*(__half2*)&f[(size_t)s3 * 32 + lane]);
            a0 += (p.x + q.x) + (u.x + v.x);
            a1 += (p.y + q.y) + (u.y + v.y);
        }
        for (; e < end; e++) {
            float2 p = __half22float2(*(__half2*)&f[(size_t)g_src[e] * 32 + lane]);
            a0 += p.x; a1 += p.y;
        }
        float iv = g_invdeg[w];
        *(__half2*)&g_aggh[(size_t)w * 64 + lane * 2] = __floats2half2_rn(a0 * iv, a1 * iv);
    }
}

// ---------------- tensor-core SAGE layer (2 K-segments, pure fp16 operands) ----------------
// rnd 0: agg_hi @ Wl ; rnd 1: x_hi @ Wr.  fp32 accumulate, bias/relu/log_softmax epilogue.
template <int CIN, int COUT, bool RELU, bool LSM, int XSEL, int OSEL, int WBASE>
__launch_bounds__(256, 1)
__global__ void k_mma(const float* __restrict__ bl, float* __restrict__ dout) {
    constexpr int PPS = CIN / 64;
    constexpr int CC  = COUT * CIN;
    constexpr int RT  = (COUT == 128) ? 2 : 1;

    extern __shared__ uint4 smemU4[];
    uint4* As0U4 = smemU4;
    uint4* Bs0U4 = As0U4 + 128 * 9;

    const __half* xh = (XSEL == 0) ? g_xh : (XSEL == 1) ? g_hah : g_hbh;

    const int tid = threadIdx.x, warp = tid >> 5, lane = tid & 31;
    const int g = lane >> 2, t = lane & 3;
    const int nb = blockIdx.x * 128;
    const int rowbase = (COUT == 128) ? (warp >> 1) * 32 : warp * 16;
    const int colbase = (COUT == 128) ? (warp & 1) * 64 : 0;

    float acc[RT][8][4];
    #pragma unroll
    for (int rt = 0; rt < RT; rt++)
        #pragma unroll
        for (int f = 0; f < 8; f++)
            #pragma unroll
            for (int j = 0; j < 4; j++) acc[rt][f][j] = 0.f;

    auto domma = [&](const unsigned* AW, const unsigned* BW) {
        #pragma unroll
        for (int kc = 0; kc < 4; kc++) {
            unsigned a[RT][4];
            #pragma unroll
            for (int rt = 0; rt < RT; rt++) {
                int r0 = rowbase + rt * 16 + g;
                a[rt][0] = AW[r0 * 36 + kc * 8 + t];
                a[rt][1] = AW[(r0 + 8) * 36 + kc * 8 + t];
                a[rt][2] = AW[r0 * 36 + kc * 8 + t + 4];
                a[rt][3] = AW[(r0 + 8) * 36 + kc * 8 + t + 4];
            }
            unsigned b[8][2];
            #pragma unroll
            for (int f = 0; f < 8; f++) {
                int br = colbase + f * 8 + g;
                b[f][0] = BW[br * 36 + kc * 8 + t];
                b[f][1] = BW[br * 36 + kc * 8 + t + 4];
            }
            #pragma unroll
            for (int rt = 0; rt < RT; rt++)
                #pragma unroll
                for (int f = 0; f < 8; f++)
                    mma16816(acc[rt][f], a[rt], b[f]);
        }
    };

    #pragma unroll
    for (int off4 = 0; off4 < PPS; off4++) {
        const int off = off4 * 64;
        #pragma unroll
        for (int rnd = 0; rnd < 2; rnd++) {
            const __half* A0 = (rnd == 0) ? g_aggh : xh;
            const int b0 = WBASE + ((rnd == 0) ? 0 : CC);   // Wl / Wr
            __syncthreads();
            #pragma unroll
            for (int it = 0; it < 4; it++) {
                int idx = tid + it * 256;
                int row = idx >> 3, q = idx & 7;
                int n = nb + row; if (n >= N_NODES) n = N_NODES - 1;
                As0U4[row * 9 + q] = ((const uint4*)A0)[(size_t)n * (CIN / 8) + off / 8 + q];
            }
            #pragma unroll
            for (int it = 0; it < COUT / 32; it++) {
                int idx = tid + it * 256;
                int row = idx >> 3, q = idx & 7;
                Bs0U4[row * 9 + q] = ((const uint4*)g_w16)[(b0 + row * CIN + off) / 8 + q];
            }
            __syncthreads();
            domma((const unsigned*)As0U4, (const unsigned*)Bs0U4);
        }
    }

    // ---------------- epilogue ----------------
    if (!LSM) {
        __half* oh = (OSEL == 1) ? g_hah : g_hbh;
        #pragma unroll
        for (int rt = 0; rt < RT; rt++) {
            int n0 = nb + rowbase + rt * 16 + g;
            int n1 = n0 + 8;
            #pragma unroll
            for (int f = 0; f < 8; f++) {
                int col = colbase + f * 8 + 2 * t;
                float2 bb = *(const float2*)&bl[col];
                float v0 = acc[rt][f][0] + bb.x, v1 = acc[rt][f][1] + bb.y;
                float v2 = acc[rt][f][2] + bb.x, v3 = acc[rt][f][3] + bb.y;
                if (RELU) {
                    v0 = fmaxf(v0, 0.f); v1 = fmaxf(v1, 0.f);
                    v2 = fmaxf(v2, 0.f); v3 = fmaxf(v3, 0.f);
                }
                if (n0 < N_NODES)
                    *(__half2*)&oh[(size_t)n0 * COUT + col] = __floats2half2_rn(v0, v1);
                if (n1 < N_NODES)
                    *(__half2*)&oh[(size_t)n1 * COUT + col] = __floats2half2_rn(v2, v3);
            }
        }
    } else {
        float v0[8], v1[8], w0[8], w1[8];
        float mxA = -1e30f, mxB = -1e30f;
        #pragma unroll
        for (int f = 0; f < 8; f++) {
            int col = f * 8 + 2 * t;
            float2 bb = *(const float2*)&bl[col];
            v0[f] = acc[0][f][0] + bb.x; v1[f] = acc[0][f][1] + bb.y;
            w0[f] = acc[0][f][2] + bb.x; w1[f] = acc[0][f][3] + bb.y;
            mxA = fmaxf(mxA, fmaxf(v0[f], v1[f]));
            mxB = fmaxf(mxB, fmaxf(w0[f], w1[f]));
        }
        #pragma unroll
        for (int m = 1; m < 4; m <<= 1) {
            mxA = fmaxf(mxA, __shfl_xor_sync(0xffffffffu, mxA, m));
            mxB = fmaxf(mxB, __shfl_xor_sync(0xffffffffu, mxB, m));
        }
        float sA = 0.f, sB = 0.f;
        #pragma unroll
        for (int f = 0; f < 8; f++) {
            sA += expf(v0[f] - mxA) + expf(v1[f] - mxA);
            sB += expf(w0[f] - mxB) + expf(w1[f] - mxB);
        }
        #pragma unroll
        for (int m = 1; m < 4; m <<= 1) {
            sA += __shfl_xor_sync(0xffffffffu, sA, m);
            sB += __shfl_xor_sync(0xffffffffu, sB, m);
        }
        float lA = mxA + logf(sA), lB = mxB + logf(sB);
        int n0 = nb + rowbase + g;
        int n1 = n0 + 8;
        if (n0 < N_NODES) {
            #pragma unroll
            for (int f = 0; f < 8; f++)
                *(float2*)&dout[(size_t)n0 * 64 + f * 8 + 2 * t] =
                    make_float2(v0[f] - lA, v1[f] - lA);
        }
        if (n1 < N_NODES) {
            #pragma unroll
            for (int f = 0; f < 8; f++)
                *(float2*)&dout[(size_t)n1 * 64 + f * 8 + 2 * t] =
                    make_float2(w0[f] - lB, w1[f] - lB);
        }
    }
}

// ---------------- launch ----------------
extern "C" void kernel_launch(void* const* d_in, const int* in_sizes, int n_in,
                              void* d_out, int out_size) {
    (void)in_sizes; (void)n_in; (void)out_size;
    const float* x   = (const float*)d_in[0];
    const void*  ei  = d_in[1];
    const float* Wl1 = (const float*)d_in[2];
    const float* bl1 = (const float*)d_in[3];
    const float* Wr1 = (const float*)d_in[4];
    const float* Wl2 = (const float*)d_in[5];
    const float* bl2 = (const float*)d_in[6];
    const float* Wr2 = (const float*)d_in[7];
    const float* Wl3 = (const float*)d_in[8];
    const float* bl3 = (const float*)d_in[9];
    const float* Wr3 = (const float*)d_in[10];
    const float* Wl4 = (const float*)d_in[11];
    const float* bl4 = (const float*)d_in[12];
    const float* Wr4 = (const float*)d_in[13];
    float* out = (float*)d_out;

    const int SMEM = 2 * 128 * 9 * 16;   // 36864 B
    cudaFuncSetAttribute(k_mma<128,128,true ,false,0,1,0    >, cudaFuncAttributeMaxDynamicSharedMemorySize, SMEM);
    cudaFuncSetAttribute(k_mma<128,128,true ,false,1,2,32768>, cudaFuncAttributeMaxDynamicSharedMemorySize, SMEM);
    cudaFuncSetAttribute(k_mma<128,64 ,true ,false,2,1,65536>, cudaFuncAttributeMaxDynamicSharedMemorySize, SMEM);
    cudaFuncSetAttribute(k_mma<64 ,64 ,false,true ,1,0,81920>, cudaFuncAttributeMaxDynamicSharedMemorySize, SMEM);

    // preprocessing + CSR build
    k_pre<<<(N_NODES * 128 + 255) / 256, 256>>>((const unsigned int*)ei, x,
                                                Wl1, Wr1, Wl2, Wr2, Wl3, Wr3, Wl4, Wr4);
    k_count<<<(N_EDGES / 4 + 255) / 256, 256>>>(ei);
    k_bsumscan<<<NBLK, 256>>>();
    k_scatter<<<NBLK, 256>>>();
    k_fill<<<(N_EDGES / 4 + 255) / 256, 256>>>(ei);

    const int AGG_GRID = (N_NODES * 32 + 255) / 256;
    const int GM = (N_NODES + 127) / 128;

    // L1
    k_agg<128, 0><<<AGG_GRID, 256>>>();
    k_mma<128, 128, true, false, 0, 1, 0><<<GM, 256, SMEM>>>(bl1, nullptr);
    // L2
    k_agg<128, 1><<<AGG_GRID, 256>>>();
    k_mma<128, 128, true, false, 1, 2, 32768><<<GM, 256, SMEM>>>(bl2, nullptr);
    // L3
    k_agg<128, 2><<<AGG_GRID, 256>>>();
    k_mma<128, 64, true, false, 2, 1, 65536><<<GM, 256, SMEM>>>(bl3, nullptr);
    // L4
    k_agg<64, 1><<<AGG_GRID, 256>>>();
    k_mma<64, 64, false, true, 1, 0, 81920><<<GM, 256, SMEM>>>(bl4, out);
}

// round 15
// speedup vs baseline: 1.8437x; 1.0110x over previous
#include <cuda_runtime.h>
#include <cuda_fp16.h>
#include <math.h>

#define N_NODES 50000
#define N_EDGES 800000
#define NBLK    ((N_NODES + 255) / 256)   // 196 scan chunks
#define CSR_GRID 296                      // 148 SMs x 2 resident blocks (guaranteed co-resident)

// ---------------- scratch ----------------
__device__ int      g_idx64;
__device__ unsigned g_bar  = 0;   // monotonic grid-barrier counter
__device__ unsigned g_done = 0;
__device__ int      g_deg[N_NODES];
__device__ float    g_invdeg[N_NODES];
__device__ int      g_rowptr[N_NODES + 1];
__device__ int      g_cursor[N_NODES];
__device__ int      g_src[N_EDGES];
__device__ int      g_bsum[256];
__device__ int      g_boff[256];
// fp16 activation planes (pure fp16 operands, fp32 accumulate in MMA)
__device__ __half g_xh  [(size_t)N_NODES * 128];
__device__ __half g_aggh[(size_t)N_NODES * 128];
__device__ __half g_hah [(size_t)N_NODES * 128];
__device__ __half g_hbh [(size_t)N_NODES * 128];
// fp16 weights: [Wl1|Wr1|Wl2|Wr2|Wl3|Wr3|Wl4|Wr4]
__device__ __half g_w16[90112];

// ---------------- helpers ----------------
__device__ __forceinline__ void mma16816(float* d, const unsigned* a, const unsigned* b) {
    asm volatile(
        "mma.sync.aligned.m16n8k16.row.col.f32.f16.f16.f32 "
        "{%0,%1,%2,%3},{%4,%5,%6,%7},{%8,%9},{%0,%1,%2,%3};"
        : "+f"(d[0]), "+f"(d[1]), "+f"(d[2]), "+f"(d[3])
        : "r"(a[0]), "r"(a[1]), "r"(a[2]), "r"(a[3]), "r"(b[0]), "r"(b[1]));
}

__device__ __forceinline__ int clampi(int v, int lo, int hi) {
    return v < lo ? lo : (v > hi ? hi : v);
}

// monotonic grid barrier: all CSR_GRID blocks are co-resident by construction
__device__ __forceinline__ void grid_barrier(unsigned target) {
    __syncthreads();
    if (threadIdx.x == 0) {
        __threadfence();
        atomicAdd(&g_bar, 1u);
        while (*(volatile unsigned*)&g_bar < target) { }
        __threadfence();
    }
    __syncthreads();
}

// ---------------- single-kernel preprocessing + CSR build ----------------
__global__ __launch_bounds__(256, 2)
void k_csr(const void* __restrict__ ei, const float* __restrict__ x,
           const float* Wl1, const float* Wr1, const float* Wl2, const float* Wr2,
           const float* Wl3, const float* Wr3, const float* Wl4, const float* Wr4) {
    __shared__ int sh[256];
    const int tid = threadIdx.x, bid = blockIdx.x;
    const int gsz = CSR_GRID * 256;
    const int gt  = bid * 256 + tid;

    // ---- phase 0: detect dtype, zero deg, convert x and weights to fp16 ----
    if (bid == 0 && tid < 32) {
        const unsigned* w = (const unsigned*)ei;
        int lane = tid;
        unsigned v = w[2 * lane + 1] | w[2 * (lane + 32) + 1] |
                     w[2 * (lane + 64) + 1] | w[2 * (lane + 96) + 1];
        unsigned any = __ballot_sync(0xffffffffu, v != 0u);
        if (lane == 0) g_idx64 = (any == 0u) ? 1 : 0;
    }
    for (int i = gt; i < N_NODES; i += gsz) g_deg[i] = 0;
    for (int i = gt; i < N_NODES * 64; i += gsz) {          // 6.4M halfs = 3.2M half2
        float2 v = ((const float2*)x)[i];
        ((__half2*)g_xh)[i] = __floats2half2_rn(v.x, v.y);
    }
    {
        const float* src[8] = {Wl1, Wr1, Wl2, Wr2, Wl3, Wr3, Wl4, Wr4};
        const int cnt[8] = {16384, 16384, 16384, 16384, 8192, 8192, 4096, 4096};
        const int dh[8]  = {0, 16384, 32768, 49152, 65536, 73728, 81920, 86016};
        #pragma unroll
        for (int s = 0; s < 8; s++)
            for (int i = gt; i < cnt[s]; i += gsz)
                g_w16[dh[s] + i] = __float2half_rn(src[s][i]);
    }
    grid_barrier(1u * CSR_GRID);

    // ---- phase 1: degree count (4 edges per iteration, vectorized) ----
    {
        const int idx64 = g_idx64;
        for (int i = gt; i < N_EDGES / 4; i += gsz) {
            int d[4];
            if (idx64) {
                const ulonglong2* p = (const ulonglong2*)((const long long*)ei + N_EDGES);
                ulonglong2 a = p[i * 2], b = p[i * 2 + 1];
                d[0] = (int)a.x; d[1] = (int)a.y; d[2] = (int)b.x; d[3] = (int)b.y;
            } else {
                int4 v = ((const int4*)((const int*)ei + N_EDGES))[i];
                d[0] = v.x; d[1] = v.y; d[2] = v.z; d[3] = v.w;
            }
            #pragma unroll
            for (int j = 0; j < 4; j++)
                atomicAdd(&g_deg[clampi(d[j], 0, N_NODES - 1)], 1);
        }
    }
    grid_barrier(2u * CSR_GRID);

    // ---- phase 2: per-chunk degree sums (chunks of 256 nodes; blocks 0..NBLK-1) ----
    if (bid < NBLK) {
        int i = bid * 256 + tid;
        sh[tid] = (i < N_NODES) ? g_deg[i] : 0;
        __syncthreads();
        for (int off = 128; off > 0; off >>= 1) {
            if (tid < off) sh[tid] += sh[tid + off];
            __syncthreads();
        }
        if (tid == 0) g_bsum[bid] = sh[0];
    }
    grid_barrier(3u * CSR_GRID);

    // ---- phase 3: block 0 scans the NBLK chunk sums ----
    if (bid == 0) {
        int v = (tid < NBLK) ? g_bsum[tid] : 0;
        sh[tid] = v;
        __syncthreads();
        for (int off = 1; off < 256; off <<= 1) {
            int u = (tid >= off) ? sh[tid - off] : 0;
            __syncthreads();
            sh[tid] += u;
            __syncthreads();
        }
        if (tid < NBLK) g_boff[tid] = sh[tid] - v;   // exclusive
        if (tid == 0)   g_rowptr[N_NODES] = N_EDGES;
    }
    grid_barrier(4u * CSR_GRID);

    // ---- phase 4: scatter rowptr/cursor/invdeg ----
    if (bid < NBLK) {
        int i = bid * 256 + tid;
        int d = (i < N_NODES) ? g_deg[i] : 0;
        sh[tid] = d;
        __syncthreads();
        for (int off = 1; off < 256; off <<= 1) {
            int u = (tid >= off) ? sh[tid - off] : 0;
            __syncthreads();
            sh[tid] += u;
            __syncthreads();
        }
        if (i < N_NODES) {
            int base = g_boff[bid] + sh[tid] - d;
            g_rowptr[i] = base;
            g_cursor[i] = base;
            g_invdeg[i] = 1.0f / fmaxf((float)d, 1.0f);
        }
    }
    grid_barrier(5u * CSR_GRID);

    // ---- phase 5: fill edge lists ----
    {
        const int idx64 = g_idx64;
        for (int i = gt; i < N_EDGES / 4; i += gsz) {
            int s[4], d[4];
            if (idx64) {
                const ulonglong2* ps = (const ulonglong2*)ei;
                const ulonglong2* pd = (const ulonglong2*)((const long long*)ei + N_EDGES);
                ulonglong2 sa = ps[i * 2], sb = ps[i * 2 + 1];
                ulonglong2 da = pd[i * 2], db = pd[i * 2 + 1];
                s[0] = (int)sa.x; s[1] = (int)sa.y; s[2] = (int)sb.x; s[3] = (int)sb.y;
                d[0] = (int)da.x; d[1] = (int)da.y; d[2] = (int)db.x; d[3] = (int)db.y;
            } else {
                int4 sv = ((const int4*)ei)[i];
                int4 dv = ((const int4*)((const int*)ei + N_EDGES))[i];
                s[0] = sv.x; s[1] = sv.y; s[2] = sv.z; s[3] = sv.w;
                d[0] = dv.x; d[1] = dv.y; d[2] = dv.z; d[3] = dv.w;
            }
            #pragma unroll
            for (int j = 0; j < 4; j++) {
                int pos = atomicAdd(&g_cursor[clampi(d[j], 0, N_NODES - 1)], 1);
                pos = clampi(pos, 0, N_EDGES - 1);
                g_src[pos] = clampi(s[j], 0, N_NODES - 1);
            }
        }
    }

    // ---- reset barrier counters for graph replay (after ALL blocks passed all barriers) ----
    __syncthreads();
    if (tid == 0) {
        __threadfence();
        unsigned v = atomicAdd(&g_done, 1u);
        if (v == CSR_GRID - 1) {
            g_bar = 0;
            g_done = 0;
            __threadfence();
        }
    }
}

// ---------------- mean aggregation: fp16 gathers (MLP 4), fp32 accumulate, fp16 out --------
// SSEL: 0 = g_xh, 1 = g_hah, 2 = g_hbh. Output: g_aggh (width C).
template <int C, int SSEL>
__global__ void k_agg() {
    const __half* feat = (SSEL == 0) ? g_xh : (SSEL == 1) ? g_hah : g_hbh;
    int w    = (blockIdx.x * blockDim.x + threadIdx.x) >> 5;
    int lane = threadIdx.x & 31;
    if (w >= N_NODES) return;
    int beg = g_rowptr[w], end = g_rowptr[w + 1];
    if (C == 128) {
        const uint2* f = (const uint2*)feat;
        float a0 = 0.f, a1 = 0.f, a2 = 0.f, a3 = 0.f;
        int e = beg;
        for (; e + 3 < end; e += 4) {
            int s0 = g_src[e],     s1 = g_src[e + 1];
            int s2 = g_src[e + 2], s3 = g_src[e + 3];
            uint2 r0 = f[(size_t)s0 * 32 + lane];
            uint2 r1 = f[(size_t)s1 * 32 + lane];
            uint2 r2 = f[(size_t)s2 * 32 + lane];
            uint2 r3 = f[(size_t)s3 * 32 + lane];
            float2 p0 = __half22float2(*(__half2*)&r0.x);
            float2 p1 = __half22float2(*(__half2*)&r0.y);
            float2 q0 = __half22float2(*(__half2*)&r1.x);
            float2 q1 = __half22float2(*(__half2*)&r1.y);
            float2 u0 = __half22float2(*(__half2*)&r2.x);
            float2 u1 = __half22float2(*(__half2*)&r2.y);
            float2 v0 = __half22float2(*(__half2*)&r3.x);
            float2 v1 = __half22float2(*(__half2*)&r3.y);
            a0 += (p0.x + q0.x) + (u0.x + v0.x);
            a1 += (p0.y + q0.y) + (u0.y + v0.y);
            a2 += (p1.x + q1.x) + (u1.x + v1.x);
            a3 += (p1.y + q1.y) + (u1.y + v1.y);
        }
        for (; e < end; e++) {
            uint2 r0 = f[(size_t)g_src[e] * 32 + lane];
            float2 p0 = __half22float2(*(__half2*)&r0.x);
            float2 p1 = __half22float2(*(__half2*)&r0.y);
            a0 += p0.x; a1 += p0.y; a2 += p1.x; a3 += p1.y;
        }
        float iv = g_invdeg[w];
        size_t base = (size_t)w * 128 + lane * 4;
        *(__half2*)&g_aggh[base]     = __floats2half2_rn(a0 * iv, a1 * iv);
        *(__half2*)&g_aggh[base + 2] = __floats2half2_rn(a2 * iv, a3 * iv);
    } else { // C == 64
        const unsigned* f = (const unsigned*)feat;
        float a0 = 0.f, a1 = 0.f;
        int e = beg;
        for (; e + 3 < end; e += 4) {
            int s0 = g_src[e],     s1 = g_src[e + 1];
            int s2 = g_src[e + 2], s3 = g_src[e + 3];
            float2 p = __half22float2(*(__half2*)&f[(size_t)s0 * 32 + lane]);
            float2 q = __half22float2(*(__half2*)&f[(size_t)s1 * 32 + lane]);
            float2 u = __half22float2(*(__half2*)&f[(size_t)s2 * 32 + lane]);
            float2 v = __half22float2(*(__half2*)&f[(size_t)s3 * 32 + lane]);
            a0 += (p.x + q.x) + (u.x + v.x);
            a1 += (p.y + q.y) + (u.y + v.y);
        }
        for (; e < end; e++) {
            float2 p = __half22float2(*(__half2*)&f[(size_t)g_src[e] * 32 + lane]);
            a0 += p.x; a1 += p.y;
        }
        float iv = g_invdeg[w];
        *(__half2*)&g_aggh[(size_t)w * 64 + lane * 2] = __floats2half2_rn(a0 * iv, a1 * iv);
    }
}

// ---------------- tensor-core SAGE layer (2 K-segments, pure fp16 operands) ----------------
// rnd 0: agg_hi @ Wl ; rnd 1: x_hi @ Wr.  fp32 accumulate, bias/relu/log_softmax epilogue.
template <int CIN, int COUT, bool RELU, bool LSM, int XSEL, int OSEL, int WBASE>
__launch_bounds__(256, 1)
__global__ void k_mma(const float* __restrict__ bl, float* __restrict__ dout) {
    constexpr int PPS = CIN / 64;
    constexpr int CC  = COUT * CIN;
    constexpr int RT  = (COUT == 128) ? 2 : 1;

    extern __shared__ uint4 smemU4[];
    uint4* As0U4 = smemU4;
    uint4* Bs0U4 = As0U4 + 128 * 9;

    const __half* xh = (XSEL == 0) ? g_xh : (XSEL == 1) ? g_hah : g_hbh;

    const int tid = threadIdx.x, warp = tid >> 5, lane = tid & 31;
    const int g = lane >> 2, t = lane & 3;
    const int nb = blockIdx.x * 128;
    const int rowbase = (COUT == 128) ? (warp >> 1) * 32 : warp * 16;
    const int colbase = (COUT == 128) ? (warp & 1) * 64 : 0;

    float acc[RT][8][4];
    #pragma unroll
    for (int rt = 0; rt < RT; rt++)
        #pragma unroll
        for (int f = 0; f < 8; f++)
            #pragma unroll
            for (int j = 0; j < 4; j++) acc[rt][f][j] = 0.f;

    auto domma = [&](const unsigned* AW, const unsigned* BW) {
        #pragma unroll
        for (int kc = 0; kc < 4; kc++) {
            unsigned a[RT][4];
            #pragma unroll
            for (int rt = 0; rt < RT; rt++) {
                int r0 = rowbase + rt * 16 + g;
                a[rt][0] = AW[r0 * 36 + kc * 8 + t];
                a[rt][1] = AW[(r0 + 8) * 36 + kc * 8 + t];
                a[rt][2] = AW[r0 * 36 + kc * 8 + t + 4];
                a[rt][3] = AW[(r0 + 8) * 36 + kc * 8 + t + 4];
            }
            unsigned b[8][2];
            #pragma unroll
            for (int f = 0; f < 8; f++) {
                int br = colbase + f * 8 + g;
                b[f][0] = BW[br * 36 + kc * 8 + t];
                b[f][1] = BW[br * 36 + kc * 8 + t + 4];
            }
            #pragma unroll
            for (int rt = 0; rt < RT; rt++)
                #pragma unroll
                for (int f = 0; f < 8; f++)
                    mma16816(acc[rt][f], a[rt], b[f]);
        }
    };

    #pragma unroll
    for (int off4 = 0; off4 < PPS; off4++) {
        const int off = off4 * 64;
        #pragma unroll
        for (int rnd = 0; rnd < 2; rnd++) {
            const __half* A0 = (rnd == 0) ? g_aggh : xh;
            const int b0 = WBASE + ((rnd == 0) ? 0 : CC);   // Wl / Wr
            __syncthreads();
            #pragma unroll
            for (int it = 0; it < 4; it++) {
                int idx = tid + it * 256;
                int row = idx >> 3, q = idx & 7;
                int n = nb + row; if (n >= N_NODES) n = N_NODES - 1;
                As0U4[row * 9 + q] = ((const uint4*)A0)[(size_t)n * (CIN / 8) + off / 8 + q];
            }
            #pragma unroll
            for (int it = 0; it < COUT / 32; it++) {
                int idx = tid + it * 256;
                int row = idx >> 3, q = idx & 7;
                Bs0U4[row * 9 + q] = ((const uint4*)g_w16)[(b0 + row * CIN + off) / 8 + q];
            }
            __syncthreads();
            domma((const unsigned*)As0U4, (const unsigned*)Bs0U4);
        }
    }

    // ---------------- epilogue ----------------
    if (!LSM) {
        __half* oh = (OSEL == 1) ? g_hah : g_hbh;
        #pragma unroll
        for (int rt = 0; rt < RT; rt++) {
            int n0 = nb + rowbase + rt * 16 + g;
            int n1 = n0 + 8;
            #pragma unroll
            for (int f = 0; f < 8; f++) {
                int col = colbase + f * 8 + 2 * t;
                float2 bb = *(const float2*)&bl[col];
                float v0 = acc[rt][f][0] + bb.x, v1 = acc[rt][f][1] + bb.y;
                float v2 = acc[rt][f][2] + bb.x, v3 = acc[rt][f][3] + bb.y;
                if (RELU) {
                    v0 = fmaxf(v0, 0.f); v1 = fmaxf(v1, 0.f);
                    v2 = fmaxf(v2, 0.f); v3 = fmaxf(v3, 0.f);
                }
                if (n0 < N_NODES)
                    *(__half2*)&oh[(size_t)n0 * COUT + col] = __floats2half2_rn(v0, v1);
                if (n1 < N_NODES)
                    *(__half2*)&oh[(size_t)n1 * COUT + col] = __floats2half2_rn(v2, v3);
            }
        }
    } else {
        float v0[8], v1[8], w0[8], w1[8];
        float mxA = -1e30f, mxB = -1e30f;
        #pragma unroll
        for (int f = 0; f < 8; f++) {
            int col = f * 8 + 2 * t;
            float2 bb = *(const float2*)&bl[col];
            v0[f] = acc[0][f][0] + bb.x; v1[f] = acc[0][f][1] + bb.y;
            w0[f] = acc[0][f][2] + bb.x; w1[f] = acc[0][f][3] + bb.y;
            mxA = fmaxf(mxA, fmaxf(v0[f], v1[f]));
            mxB = fmaxf(mxB, fmaxf(w0[f], w1[f]));
        }
        #pragma unroll
        for (int m = 1; m < 4; m <<= 1) {
            mxA = fmaxf(mxA, __shfl_xor_sync(0xffffffffu, mxA, m));
            mxB = fmaxf(mxB, __shfl_xor_sync(0xffffffffu, mxB, m));
        }
        float sA = 0.f, sB = 0.f;
        #pragma unroll
        for (int f = 0; f < 8; f++) {
            sA += expf(v0[f] - mxA) + expf(v1[f] - mxA);
            sB += expf(w0[f] - mxB) + expf(w1[f] - mxB);
        }
        #pragma unroll
        for (int m = 1; m < 4; m <<= 1) {
            sA += __shfl_xor_sync(0xffffffffu, sA, m);
            sB += __shfl_xor_sync(0xffffffffu, sB, m);
        }
        float lA = mxA + logf(sA), lB = mxB + logf(sB);
        int n0 = nb + rowbase + g;
        int n1 = n0 + 8;
        if (n0 < N_NODES) {
            #pragma unroll
            for (int f = 0; f < 8; f++)
                *(float2*)&dout[(size_t)n0 * 64 + f * 8 + 2 * t] =
                    make_float2(v0[f] - lA, v1[f] - lA);
        }
        if (n1 < N_NODES) {
            #pragma unroll
            for (int f = 0; f < 8; f++)
                *(float2*)&dout[(size_t)n1 * 64 + f * 8 + 2 * t] =
                    make_float2(w0[f] - lB, w1[f] - lB);
        }
    }
}

// ---------------- launch ----------------
extern "C" void kernel_launch(void* const* d_in, const int* in_sizes, int n_in,
                              void* d_out, int out_size) {
    (void)in_sizes; (void)n_in; (void)out_size;
    const float* x   = (const float*)d_in[0];
    const void*  ei  = d_in[1];
    const float* Wl1 = (const float*)d_in[2];
    const float* bl1 = (const float*)d_in[3];
    const float* Wr1 = (const float*)d_in[4];
    const float* Wl2 = (const float*)d_in[5];
    const float* bl2 = (const float*)d_in[6];
    const float* Wr2 = (const float*)d_in[7];
    const float* Wl3 = (const float*)d_in[8];
    const float* bl3 = (const float*)d_in[9];
    const float* Wr3 = (const float*)d_in[10];
    const float* Wl4 = (const float*)d_in[11];
    const float* bl4 = (const float*)d_in[12];
    const float* Wr4 = (const float*)d_in[13];
    float* out = (float*)d_out;

    const int SMEM = 2 * 128 * 9 * 16;   // 36864 B
    cudaFuncSetAttribute(k_mma<128,128,true ,false,0,1,0    >, cudaFuncAttributeMaxDynamicSharedMemorySize, SMEM);
    cudaFuncSetAttribute(k_mma<128,128,true ,false,1,2,32768>, cudaFuncAttributeMaxDynamicSharedMemorySize, SMEM);
    cudaFuncSetAttribute(k_mma<128,64 ,true ,false,2,1,65536>, cudaFuncAttributeMaxDynamicSharedMemorySize, SMEM);
    cudaFuncSetAttribute(k_mma<64 ,64 ,false,true ,1,0,81920>, cudaFuncAttributeMaxDynamicSharedMemorySize, SMEM);

    // single-kernel preprocessing + CSR build (296 co-resident blocks, in-kernel barriers)
    k_csr<<<CSR_GRID, 256>>>(ei, x, Wl1, Wr1, Wl2, Wr2, Wl3, Wr3, Wl4, Wr4);

    const int AGG_GRID = (N_NODES * 32 + 255) / 256;
    const int GM = (N_NODES + 127) / 128;

    // L1
    k_agg<128, 0><<<AGG_GRID, 256>>>();
    k_mma<128, 128, true, false, 0, 1, 0><<<GM, 256, SMEM>>>(bl1, nullptr);
    // L2
    k_agg<128, 1><<<AGG_GRID, 256>>>();
    k_mma<128, 128, true, false, 1, 2, 32768><<<GM, 256, SMEM>>>(bl2, nullptr);
    // L3
    k_agg<128, 2><<<AGG_GRID, 256>>>();
    k_mma<128, 64, true, false, 2, 1, 65536><<<GM, 256, SMEM>>>(bl3, nullptr);
    // L4
    k_agg<64, 1><<<AGG_GRID, 256>>>();
    k_mma<64, 64, false, true, 1, 0, 81920><<<GM, 256, SMEM>>>(bl4, out);
}

// round 16
// speedup vs baseline: 1.9292x; 1.0464x over previous
#include <cuda_runtime.h>
#include <cuda_fp16.h>
#include <math.h>

#define N_NODES 50000
#define N_EDGES 800000
#define NBLK    ((N_NODES + 255) / 256)   // 196 scan chunks
#define CSR_GRID 296                      // 148 SMs x 2 resident blocks (guaranteed co-resident)

// ---------------- scratch ----------------
__device__ int      g_idx64;
__device__ unsigned g_bar  = 0;   // monotonic grid-barrier counter
__device__ unsigned g_done = 0;
__device__ int      g_deg[N_NODES];
__device__ float    g_invdeg[N_NODES];
__device__ int      g_rowptr[N_NODES + 1];
__device__ int      g_cursor[N_NODES];
__device__ int      g_src[N_EDGES];
__device__ int      g_bsum[256];
__device__ int      g_boff[256];
// fp16 activation planes (pure fp16 operands, fp32 accumulate in MMA)
__device__ __half g_xh  [(size_t)N_NODES * 128];
__device__ __half g_aggh[(size_t)N_NODES * 128];
__device__ __half g_hah [(size_t)N_NODES * 128];
__device__ __half g_hbh [(size_t)N_NODES * 128];
// fp16 weights: [Wl1|Wr1|Wl2|Wr2|Wl3|Wr3|Wl4|Wr4]
__device__ __half g_w16[90112];

// ---------------- helpers ----------------
__device__ __forceinline__ void mma16816(float* d, const unsigned* a, const unsigned* b) {
    asm volatile(
        "mma.sync.aligned.m16n8k16.row.col.f32.f16.f16.f32 "
        "{%0,%1,%2,%3},{%4,%5,%6,%7},{%8,%9},{%0,%1,%2,%3};"
        : "+f"(d[0]), "+f"(d[1]), "+f"(d[2]), "+f"(d[3])
        : "r"(a[0]), "r"(a[1]), "r"(a[2]), "r"(a[3]), "r"(b[0]), "r"(b[1]));
}

__device__ __forceinline__ int clampi(int v, int lo, int hi) {
    return v < lo ? lo : (v > hi ? hi : v);
}

// monotonic grid barrier: all CSR_GRID blocks are co-resident by construction
__device__ __forceinline__ void grid_barrier(unsigned target) {
    __syncthreads();
    if (threadIdx.x == 0) {
        __threadfence();
        atomicAdd(&g_bar, 1u);
        while (*(volatile unsigned*)&g_bar < target) { }
        __threadfence();
    }
    __syncthreads();
}

// ---------------- single-kernel preprocessing + CSR build ----------------
__global__ __launch_bounds__(256, 2)
void k_csr(const void* __restrict__ ei, const float* __restrict__ x,
           const float* Wl1, const float* Wr1, const float* Wl2, const float* Wr2,
           const float* Wl3, const float* Wr3, const float* Wl4, const float* Wr4) {
    __shared__ int sh[256];
    const int tid = threadIdx.x, bid = blockIdx.x;
    const int gsz = CSR_GRID * 256;
    const int gt  = bid * 256 + tid;

    // ---- phase 0: detect dtype, zero deg, convert x and weights to fp16 ----
    if (bid == 0 && tid < 32) {
        const unsigned* w = (const unsigned*)ei;
        int lane = tid;
        unsigned v = w[2 * lane + 1] | w[2 * (lane + 32) + 1] |
                     w[2 * (lane + 64) + 1] | w[2 * (lane + 96) + 1];
        unsigned any = __ballot_sync(0xffffffffu, v != 0u);
        if (lane == 0) g_idx64 = (any == 0u) ? 1 : 0;
    }
    for (int i = gt; i < N_NODES; i += gsz) g_deg[i] = 0;
    for (int i = gt; i < N_NODES * 64; i += gsz) {
        float2 v = ((const float2*)x)[i];
        ((__half2*)g_xh)[i] = __floats2half2_rn(v.x, v.y);
    }
    {
        const float* src[8] = {Wl1, Wr1, Wl2, Wr2, Wl3, Wr3, Wl4, Wr4};
        const int cnt[8] = {16384, 16384, 16384, 16384, 8192, 8192, 4096, 4096};
        const int dh[8]  = {0, 16384, 32768, 49152, 65536, 73728, 81920, 86016};
        #pragma unroll
        for (int s = 0; s < 8; s++)
            for (int i = gt; i < cnt[s]; i += gsz)
                g_w16[dh[s] + i] = __float2half_rn(src[s][i]);
    }
    grid_barrier(1u * CSR_GRID);

    // ---- phase 1: degree count ----
    {
        const int idx64 = g_idx64;
        for (int i = gt; i < N_EDGES / 4; i += gsz) {
            int d[4];
            if (idx64) {
                const ulonglong2* p = (const ulonglong2*)((const long long*)ei + N_EDGES);
                ulonglong2 a = p[i * 2], b = p[i * 2 + 1];
                d[0] = (int)a.x; d[1] = (int)a.y; d[2] = (int)b.x; d[3] = (int)b.y;
            } else {
                int4 v = ((const int4*)((const int*)ei + N_EDGES))[i];
                d[0] = v.x; d[1] = v.y; d[2] = v.z; d[3] = v.w;
            }
            #pragma unroll
            for (int j = 0; j < 4; j++)
                atomicAdd(&g_deg[clampi(d[j], 0, N_NODES - 1)], 1);
        }
    }
    grid_barrier(2u * CSR_GRID);

    // ---- phase 2: per-chunk degree sums ----
    if (bid < NBLK) {
        int i = bid * 256 + tid;
        sh[tid] = (i < N_NODES) ? g_deg[i] : 0;
        __syncthreads();
        for (int off = 128; off > 0; off >>= 1) {
            if (tid < off) sh[tid] += sh[tid + off];
            __syncthreads();
        }
        if (tid == 0) g_bsum[bid] = sh[0];
    }
    grid_barrier(3u * CSR_GRID);

    // ---- phase 3: block 0 scans the chunk sums ----
    if (bid == 0) {
        int v = (tid < NBLK) ? g_bsum[tid] : 0;
        sh[tid] = v;
        __syncthreads();
        for (int off = 1; off < 256; off <<= 1) {
            int u = (tid >= off) ? sh[tid - off] : 0;
            __syncthreads();
            sh[tid] += u;
            __syncthreads();
        }
        if (tid < NBLK) g_boff[tid] = sh[tid] - v;
        if (tid == 0)   g_rowptr[N_NODES] = N_EDGES;
    }
    grid_barrier(4u * CSR_GRID);

    // ---- phase 4: scatter rowptr/cursor/invdeg ----
    if (bid < NBLK) {
        int i = bid * 256 + tid;
        int d = (i < N_NODES) ? g_deg[i] : 0;
        sh[tid] = d;
        __syncthreads();
        for (int off = 1; off < 256; off <<= 1) {
            int u = (tid >= off) ? sh[tid - off] : 0;
            __syncthreads();
            sh[tid] += u;
            __syncthreads();
        }
        if (i < N_NODES) {
            int base = g_boff[bid] + sh[tid] - d;
            g_rowptr[i] = base;
            g_cursor[i] = base;
            g_invdeg[i] = 1.0f / fmaxf((float)d, 1.0f);
        }
    }
    grid_barrier(5u * CSR_GRID);

    // ---- phase 5: fill edge lists ----
    {
        const int idx64 = g_idx64;
        for (int i = gt; i < N_EDGES / 4; i += gsz) {
            int s[4], d[4];
            if (idx64) {
                const ulonglong2* ps = (const ulonglong2*)ei;
                const ulonglong2* pd = (const ulonglong2*)((const long long*)ei + N_EDGES);
                ulonglong2 sa = ps[i * 2], sb = ps[i * 2 + 1];
                ulonglong2 da = pd[i * 2], db = pd[i * 2 + 1];
                s[0] = (int)sa.x; s[1] = (int)sa.y; s[2] = (int)sb.x; s[3] = (int)sb.y;
                d[0] = (int)da.x; d[1] = (int)da.y; d[2] = (int)db.x; d[3] = (int)db.y;
            } else {
                int4 sv = ((const int4*)ei)[i];
                int4 dv = ((const int4*)((const int*)ei + N_EDGES))[i];
                s[0] = sv.x; s[1] = sv.y; s[2] = sv.z; s[3] = sv.w;
                d[0] = dv.x; d[1] = dv.y; d[2] = dv.z; d[3] = dv.w;
            }
            #pragma unroll
            for (int j = 0; j < 4; j++) {
                int pos = atomicAdd(&g_cursor[clampi(d[j], 0, N_NODES - 1)], 1);
                pos = clampi(pos, 0, N_EDGES - 1);
                g_src[pos] = clampi(s[j], 0, N_NODES - 1);
            }
        }
    }

    // ---- reset barrier counters for graph replay ----
    __syncthreads();
    if (tid == 0) {
        __threadfence();
        unsigned v = atomicAdd(&g_done, 1u);
        if (v == CSR_GRID - 1) {
            g_bar = 0;
            g_done = 0;
            __threadfence();
        }
    }
}

// ---------------- mean aggregation: fp16 gathers, HADD2 group-of-4 tree, fp32 accumulate ----
// SSEL: 0 = g_xh, 1 = g_hah, 2 = g_hbh. Output: g_aggh (width C).
template <int C, int SSEL>
__global__ void k_agg() {
    const __half* feat = (SSEL == 0) ? g_xh : (SSEL == 1) ? g_hah : g_hbh;
    int w    = (blockIdx.x * blockDim.x + threadIdx.x) >> 5;
    int lane = threadIdx.x & 31;
    if (w >= N_NODES) return;
    int beg = g_rowptr[w], end = g_rowptr[w + 1];
    if (C == 128) {
        const uint2* f = (const uint2*)feat;
        float a0 = 0.f, a1 = 0.f, a2 = 0.f, a3 = 0.f;
        int e = beg;
        for (; e + 3 < end; e += 4) {
            int s0 = g_src[e],     s1 = g_src[e + 1];
            int s2 = g_src[e + 2], s3 = g_src[e + 3];
            uint2 r0 = f[(size_t)s0 * 32 + lane];
            uint2 r1 = f[(size_t)s1 * 32 + lane];
            uint2 r2 = f[(size_t)s2 * 32 + lane];
            uint2 r3 = f[(size_t)s3 * 32 + lane];
            // fp16 pairwise tree over the 4 edges (6 HADD2), then one convert+add
            __half2 lo = __hadd2(__hadd2(*(__half2*)&r0.x, *(__half2*)&r1.x),
                                 __hadd2(*(__half2*)&r2.x, *(__half2*)&r3.x));
            __half2 hi = __hadd2(__hadd2(*(__half2*)&r0.y, *(__half2*)&r1.y),
                                 __hadd2(*(__half2*)&r2.y, *(__half2*)&r3.y));
            float2 pl = __half22float2(lo);
            float2 ph = __half22float2(hi);
            a0 += pl.x; a1 += pl.y; a2 += ph.x; a3 += ph.y;
        }
        for (; e < end; e++) {
            uint2 r0 = f[(size_t)g_src[e] * 32 + lane];
            float2 p0 = __half22float2(*(__half2*)&r0.x);
            float2 p1 = __half22float2(*(__half2*)&r0.y);
            a0 += p0.x; a1 += p0.y; a2 += p1.x; a3 += p1.y;
        }
        float iv = g_invdeg[w];
        size_t base = (size_t)w * 128 + lane * 4;
        *(__half2*)&g_aggh[base]     = __floats2half2_rn(a0 * iv, a1 * iv);
        *(__half2*)&g_aggh[base + 2] = __floats2half2_rn(a2 * iv, a3 * iv);
    } else { // C == 64
        const unsigned* f = (const unsigned*)feat;
        float a0 = 0.f, a1 = 0.f;
        int e = beg;
        for (; e + 3 < end; e += 4) {
            int s0 = g_src[e],     s1 = g_src[e + 1];
            int s2 = g_src[e + 2], s3 = g_src[e + 3];
            unsigned r0 = f[(size_t)s0 * 32 + lane];
            unsigned r1 = f[(size_t)s1 * 32 + lane];
            unsigned r2 = f[(size_t)s2 * 32 + lane];
            unsigned r3 = f[(size_t)s3 * 32 + lane];
            __half2 s = __hadd2(__hadd2(*(__half2*)&r0, *(__half2*)&r1),
                                __hadd2(*(__half2*)&r2, *(__half2*)&r3));
            float2 p = __half22float2(s);
            a0 += p.x; a1 += p.y;
        }
        for (; e < end; e++) {
            unsigned r = f[(size_t)g_src[e] * 32 + lane];
            float2 p = __half22float2(*(__half2*)&r);
            a0 += p.x; a1 += p.y;
        }
        float iv = g_invdeg[w];
        *(__half2*)&g_aggh[(size_t)w * 64 + lane * 2] = __floats2half2_rn(a0 * iv, a1 * iv);
    }
}

// ---------------- tensor-core SAGE layer (2 K-segments, pure fp16 operands) ----------------
// rnd 0: agg_hi @ Wl ; rnd 1: x_hi @ Wr.  fp32 accumulate, bias/relu/log_softmax epilogue.
template <int CIN, int COUT, bool RELU, bool LSM, int XSEL, int OSEL, int WBASE>
__launch_bounds__(256, 1)
__global__ void k_mma(const float* __restrict__ bl, float* __restrict__ dout) {
    constexpr int PPS = CIN / 64;
    constexpr int CC  = COUT * CIN;
    constexpr int RT  = (COUT == 128) ? 2 : 1;

    extern __shared__ uint4 smemU4[];
    uint4* As0U4 = smemU4;
    uint4* Bs0U4 = As0U4 + 128 * 9;

    const __half* xh = (XSEL == 0) ? g_xh : (XSEL == 1) ? g_hah : g_hbh;

    const int tid = threadIdx.x, warp = tid >> 5, lane = tid & 31;
    const int g = lane >> 2, t = lane & 3;
    const int nb = blockIdx.x * 128;
    const int rowbase = (COUT == 128) ? (warp >> 1) * 32 : warp * 16;
    const int colbase = (COUT == 128) ? (warp & 1) * 64 : 0;

    float acc[RT][8][4];
    #pragma unroll
    for (int rt = 0; rt < RT; rt++)
        #pragma unroll
        for (int f = 0; f < 8; f++)
            #pragma unroll
            for (int j = 0; j < 4; j++) acc[rt][f][j] = 0.f;

    auto domma = [&](const unsigned* AW, const unsigned* BW) {
        #pragma unroll
        for (int kc = 0; kc < 4; kc++) {
            unsigned a[RT][4];
            #pragma unroll
            for (int rt = 0; rt < RT; rt++) {
                int r0 = rowbase + rt * 16 + g;
                a[rt][0] = AW[r0 * 36 + kc * 8 + t];
                a[rt][1] = AW[(r0 + 8) * 36 + kc * 8 + t];
                a[rt][2] = AW[r0 * 36 + kc * 8 + t + 4];
                a[rt][3] = AW[(r0 + 8) * 36 + kc * 8 + t + 4];
            }
            unsigned b[8][2];
            #pragma unroll
            for (int f = 0; f < 8; f++) {
                int br = colbase + f * 8 + g;
                b[f][0] = BW[br * 36 + kc * 8 + t];
                b[f][1] = BW[br * 36 + kc * 8 + t + 4];
            }
            #pragma unroll
            for (int rt = 0; rt < RT; rt++)
                #pragma unroll
                for (int f = 0; f < 8; f++)
                    mma16816(acc[rt][f], a[rt], b[f]);
        }
    };

    #pragma unroll
    for (int off4 = 0; off4 < PPS; off4++) {
        const int off = off4 * 64;
        #pragma unroll
        for (int rnd = 0; rnd < 2; rnd++) {
            const __half* A0 = (rnd == 0) ? g_aggh : xh;
            const int b0 = WBASE + ((rnd == 0) ? 0 : CC);   // Wl / Wr
            __syncthreads();
            #pragma unroll
            for (int it = 0; it < 4; it++) {
                int idx = tid + it * 256;
                int row = idx >> 3, q = idx & 7;
                int n = nb + row; if (n >= N_NODES) n = N_NODES - 1;
                As0U4[row * 9 + q] = ((const uint4*)A0)[(size_t)n * (CIN / 8) + off / 8 + q];
            }
            #pragma unroll
            for (int it = 0; it < COUT / 32; it++) {
                int idx = tid + it * 256;
                int row = idx >> 3, q = idx & 7;
                Bs0U4[row * 9 + q] = ((const uint4*)g_w16)[(b0 + row * CIN + off) / 8 + q];
            }
            __syncthreads();
            domma((const unsigned*)As0U4, (const unsigned*)Bs0U4);
        }
    }

    // ---------------- epilogue ----------------
    if (!LSM) {
        __half* oh = (OSEL == 1) ? g_hah : g_hbh;
        #pragma unroll
        for (int rt = 0; rt < RT; rt++) {
            int n0 = nb + rowbase + rt * 16 + g;
            int n1 = n0 + 8;
            #pragma unroll
            for (int f = 0; f < 8; f++) {
                int col = colbase + f * 8 + 2 * t;
                float2 bb = *(const float2*)&bl[col];
                float v0 = acc[rt][f][0] + bb.x, v1 = acc[rt][f][1] + bb.y;
                float v2 = acc[rt][f][2] + bb.x, v3 = acc[rt][f][3] + bb.y;
                if (RELU) {
                    v0 = fmaxf(v0, 0.f); v1 = fmaxf(v1, 0.f);
                    v2 = fmaxf(v2, 0.f); v3 = fmaxf(v3, 0.f);
                }
                if (n0 < N_NODES)
                    *(__half2*)&oh[(size_t)n0 * COUT + col] = __floats2half2_rn(v0, v1);
                if (n1 < N_NODES)
                    *(__half2*)&oh[(size_t)n1 * COUT + col] = __floats2half2_rn(v2, v3);
            }
        }
    } else {
        float v0[8], v1[8], w0[8], w1[8];
        float mxA = -1e30f, mxB = -1e30f;
        #pragma unroll
        for (int f = 0; f < 8; f++) {
            int col = f * 8 + 2 * t;
            float2 bb = *(const float2*)&bl[col];
            v0[f] = acc[0][f][0] + bb.x; v1[f] = acc[0][f][1] + bb.y;
            w0[f] = acc[0][f][2] + bb.x; w1[f] = acc[0][f][3] + bb.y;
            mxA = fmaxf(mxA, fmaxf(v0[f], v1[f]));
            mxB = fmaxf(mxB, fmaxf(w0[f], w1[f]));
        }
        #pragma unroll
        for (int m = 1; m < 4; m <<= 1) {
            mxA = fmaxf(mxA, __shfl_xor_sync(0xffffffffu, mxA, m));
            mxB = fmaxf(mxB, __shfl_xor_sync(0xffffffffu, mxB, m));
        }
        float sA = 0.f, sB = 0.f;
        #pragma unroll
        for (int f = 0; f < 8; f++) {
            sA += expf(v0[f] - mxA) + expf(v1[f] - mxA);
            sB += expf(w0[f] - mxB) + expf(w1[f] - mxB);
        }
        #pragma unroll
        for (int m = 1; m < 4; m <<= 1) {
            sA += __shfl_xor_sync(0xffffffffu, sA, m);
            sB += __shfl_xor_sync(0xffffffffu, sB, m);
        }
        float lA = mxA + logf(sA), lB = mxB + logf(sB);
        int n0 = nb + rowbase + g;
        int n1 = n0 + 8;
        if (n0 < N_NODES) {
            #pragma unroll
            for (int f = 0; f < 8; f++)
                *(float2*)&dout[(size_t)n0 * 64 + f * 8 + 2 * t] =
                    make_float2(v0[f] - lA, v1[f] - lA);
        }
        if (n1 < N_NODES) {
            #pragma unroll
            for (int f = 0; f < 8; f++)
                *(float2*)&dout[(size_t)n1 * 64 + f * 8 + 2 * t] =
                    make_float2(w0[f] - lB, w1[f] - lB);
        }
    }
}

// ---------------- launch ----------------
extern "C" void kernel_launch(void* const* d_in, const int* in_sizes, int n_in,
                              void* d_out, int out_size) {
    (void)in_sizes; (void)n_in; (void)out_size;
    const float* x   = (const float*)d_in[0];
    const void*  ei  = d_in[1];
    const float* Wl1 = (const float*)d_in[2];
    const float* bl1 = (const float*)d_in[3];
    const float* Wr1 = (const float*)d_in[4];
    const float* Wl2 = (const float*)d_in[5];
    const float* bl2 = (const float*)d_in[6];
    const float* Wr2 = (const float*)d_in[7];
    const float* Wl3 = (const float*)d_in[8];
    const float* bl3 = (const float*)d_in[9];
    const float* Wr3 = (const float*)d_in[10];
    const float* Wl4 = (const float*)d_in[11];
    const float* bl4 = (const float*)d_in[12];
    const float* Wr4 = (const float*)d_in[13];
    float* out = (float*)d_out;

    const int SMEM = 2 * 128 * 9 * 16;   // 36864 B
    cudaFuncSetAttribute(k_mma<128,128,true ,false,0,1,0    >, cudaFuncAttributeMaxDynamicSharedMemorySize, SMEM);
    cudaFuncSetAttribute(k_mma<128,128,true ,false,1,2,32768>, cudaFuncAttributeMaxDynamicSharedMemorySize, SMEM);
    cudaFuncSetAttribute(k_mma<128,64 ,true ,false,2,1,65536>, cudaFuncAttributeMaxDynamicSharedMemorySize, SMEM);
    cudaFuncSetAttribute(k_mma<64 ,64 ,false,true ,1,0,81920>, cudaFuncAttributeMaxDynamicSharedMemorySize, SMEM);

    // single-kernel preprocessing + CSR build
    k_csr<<<CSR_GRID, 256>>>(ei, x, Wl1, Wr1, Wl2, Wr2, Wl3, Wr3, Wl4, Wr4);

    const int AGG_GRID = (N_NODES * 32 + 255) / 256;
    const int GM = (N_NODES + 127) / 128;

    // L1
    k_agg<128, 0><<<AGG_GRID, 256>>>();
    k_mma<128, 128, true, false, 0, 1, 0><<<GM, 256, SMEM>>>(bl1, nullptr);
    // L2
    k_agg<128, 1><<<AGG_GRID, 256>>>();
    k_mma<128, 128, true, false, 1, 2, 32768><<<GM, 256, SMEM>>>(bl2, nullptr);
    // L3
    k_agg<128, 2><<<AGG_GRID, 256>>>();
    k_mma<128, 64, true, false, 2, 1, 65536><<<GM, 256, SMEM>>>(bl3, nullptr);
    // L4
    k_agg<64, 1><<<AGG_GRID, 256>>>();
    k_mma<64, 64, false, true, 1, 0, 81920><<<GM, 256, SMEM>>>(bl4, out);
}

// round 17
// speedup vs baseline: 2.0424x; 1.0587x over previous
#include <cuda_runtime.h>
#include <cuda_fp16.h>
#include <math.h>

#define N_NODES 50000
#define N_EDGES 800000
#define NBLK    ((N_NODES + 255) / 256)   // 196 scan chunks
#define CSR_GRID 296                      // 148 SMs x 2 resident blocks (guaranteed co-resident)

// ---------------- scratch ----------------
__device__ int      g_idx64;
__device__ unsigned g_bar  = 0;   // monotonic grid-barrier counter
__device__ unsigned g_done = 0;
__device__ int      g_deg[N_NODES];
__device__ float    g_invdeg[N_NODES];
__device__ int      g_rowptr[N_NODES + 1];
__device__ int      g_cursor[N_NODES];
__device__ int      g_src[N_EDGES];       // stores source node id * 32 (row offset in 8B/4B units)
__device__ int      g_bsum[256];
__device__ int      g_boff[256];
// fp16 activation planes (pure fp16 operands, fp32 accumulate in MMA)
__device__ __half g_xh  [(size_t)N_NODES * 128];
__device__ __half g_aggh[(size_t)N_NODES * 128];
__device__ __half g_hah [(size_t)N_NODES * 128];
__device__ __half g_hbh [(size_t)N_NODES * 128];
// fp16 weights: [Wl1|Wr1|Wl2|Wr2|Wl3|Wr3|Wl4|Wr4]
__device__ __half g_w16[90112];

// ---------------- helpers ----------------
__device__ __forceinline__ void mma16816(float* d, const unsigned* a, const unsigned* b) {
    asm volatile(
        "mma.sync.aligned.m16n8k16.row.col.f32.f16.f16.f32 "
        "{%0,%1,%2,%3},{%4,%5,%6,%7},{%8,%9},{%0,%1,%2,%3};"
        : "+f"(d[0]), "+f"(d[1]), "+f"(d[2]), "+f"(d[3])
        : "r"(a[0]), "r"(a[1]), "r"(a[2]), "r"(a[3]), "r"(b[0]), "r"(b[1]));
}

__device__ __forceinline__ int clampi(int v, int lo, int hi) {
    return v < lo ? lo : (v > hi ? hi : v);
}

// monotonic grid barrier: all CSR_GRID blocks are co-resident by construction
__device__ __forceinline__ void grid_barrier(unsigned target) {
    __syncthreads();
    if (threadIdx.x == 0) {
        __threadfence();
        atomicAdd(&g_bar, 1u);
        while (*(volatile unsigned*)&g_bar < target) { }
        __threadfence();
    }
    __syncthreads();
}

// ---------------- single-kernel preprocessing + CSR build ----------------
__global__ __launch_bounds__(256, 2)
void k_csr(const void* __restrict__ ei, const float* __restrict__ x,
           const float* Wl1, const float* Wr1, const float* Wl2, const float* Wr2,
           const float* Wl3, const float* Wr3, const float* Wl4, const float* Wr4) {
    __shared__ int sh[256];
    const int tid = threadIdx.x, bid = blockIdx.x;
    const int gsz = CSR_GRID * 256;
    const int gt  = bid * 256 + tid;

    // ---- phase 0: detect dtype, zero deg, convert x and weights to fp16 ----
    if (bid == 0 && tid < 32) {
        const unsigned* w = (const unsigned*)ei;
        int lane = tid;
        unsigned v = w[2 * lane + 1] | w[2 * (lane + 32) + 1] |
                     w[2 * (lane + 64) + 1] | w[2 * (lane + 96) + 1];
        unsigned any = __ballot_sync(0xffffffffu, v != 0u);
        if (lane == 0) g_idx64 = (any == 0u) ? 1 : 0;
    }
    for (int i = gt; i < N_NODES; i += gsz) g_deg[i] = 0;
    for (int i = gt; i < N_NODES * 64; i += gsz) {
        float2 v = ((const float2*)x)[i];
        ((__half2*)g_xh)[i] = __floats2half2_rn(v.x, v.y);
    }
    {
        const float* src[8] = {Wl1, Wr1, Wl2, Wr2, Wl3, Wr3, Wl4, Wr4};
        const int cnt[8] = {16384, 16384, 16384, 16384, 8192, 8192, 4096, 4096};
        const int dh[8]  = {0, 16384, 32768, 49152, 65536, 73728, 81920, 86016};
        #pragma unroll
        for (int s = 0; s < 8; s++)
            for (int i = gt; i < cnt[s]; i += gsz)
                g_w16[dh[s] + i] = __float2half_rn(src[s][i]);
    }
    grid_barrier(1u * CSR_GRID);

    // ---- phase 1: degree count ----
    {
        const int idx64 = g_idx64;
        for (int i = gt; i < N_EDGES / 4; i += gsz) {
            int d[4];
            if (idx64) {
                const ulonglong2* p = (const ulonglong2*)((const long long*)ei + N_EDGES);
                ulonglong2 a = p[i * 2], b = p[i * 2 + 1];
                d[0] = (int)a.x; d[1] = (int)a.y; d[2] = (int)b.x; d[3] = (int)b.y;
            } else {
                int4 v = ((const int4*)((const int*)ei + N_EDGES))[i];
                d[0] = v.x; d[1] = v.y; d[2] = v.z; d[3] = v.w;
            }
            #pragma unroll
            for (int j = 0; j < 4; j++)
                atomicAdd(&g_deg[clampi(d[j], 0, N_NODES - 1)], 1);
        }
    }
    grid_barrier(2u * CSR_GRID);

    // ---- phase 2: per-chunk degree sums ----
    if (bid < NBLK) {
        int i = bid * 256 + tid;
        sh[tid] = (i < N_NODES) ? g_deg[i] : 0;
        __syncthreads();
        for (int off = 128; off > 0; off >>= 1) {
            if (tid < off) sh[tid] += sh[tid + off];
            __syncthreads();
        }
        if (tid == 0) g_bsum[bid] = sh[0];
    }
    grid_barrier(3u * CSR_GRID);

    // ---- phase 3: block 0 scans the chunk sums ----
    if (bid == 0) {
        int v = (tid < NBLK) ? g_bsum[tid] : 0;
        sh[tid] = v;
        __syncthreads();
        for (int off = 1; off < 256; off <<= 1) {
            int u = (tid >= off) ? sh[tid - off] : 0;
            __syncthreads();
            sh[tid] += u;
            __syncthreads();
        }
        if (tid < NBLK) g_boff[tid] = sh[tid] - v;
        if (tid == 0)   g_rowptr[N_NODES] = N_EDGES;
    }
    grid_barrier(4u * CSR_GRID);

    // ---- phase 4: scatter rowptr/cursor/invdeg ----
    if (bid < NBLK) {
        int i = bid * 256 + tid;
        int d = (i < N_NODES) ? g_deg[i] : 0;
        sh[tid] = d;
        __syncthreads();
        for (int off = 1; off < 256; off <<= 1) {
            int u = (tid >= off) ? sh[tid - off] : 0;
            __syncthreads();
            sh[tid] += u;
            __syncthreads();
        }
        if (i < N_NODES) {
            int base = g_boff[bid] + sh[tid] - d;
            g_rowptr[i] = base;
            g_cursor[i] = base;
            g_invdeg[i] = 1.0f / fmaxf((float)d, 1.0f);
        }
    }
    grid_barrier(5u * CSR_GRID);

    // ---- phase 5: fill edge lists (store PRE-SCALED source offsets: id*32) ----
    {
        const int idx64 = g_idx64;
        for (int i = gt; i < N_EDGES / 4; i += gsz) {
            int s[4], d[4];
            if (idx64) {
                const ulonglong2* ps = (const ulonglong2*)ei;
                const ulonglong2* pd = (const ulonglong2*)((const long long*)ei + N_EDGES);
                ulonglong2 sa = ps[i * 2], sb = ps[i * 2 + 1];
                ulonglong2 da = pd[i * 2], db = pd[i * 2 + 1];
                s[0] = (int)sa.x; s[1] = (int)sa.y; s[2] = (int)sb.x; s[3] = (int)sb.y;
                d[0] = (int)da.x; d[1] = (int)da.y; d[2] = (int)db.x; d[3] = (int)db.y;
            } else {
                int4 sv = ((const int4*)ei)[i];
                int4 dv = ((const int4*)((const int*)ei + N_EDGES))[i];
                s[0] = sv.x; s[1] = sv.y; s[2] = sv.z; s[3] = sv.w;
                d[0] = dv.x; d[1] = dv.y; d[2] = dv.z; d[3] = dv.w;
            }
            #pragma unroll
            for (int j = 0; j < 4; j++) {
                int pos = atomicAdd(&g_cursor[clampi(d[j], 0, N_NODES - 1)], 1);
                pos = clampi(pos, 0, N_EDGES - 1);
                g_src[pos] = clampi(s[j], 0, N_NODES - 1) * 32;
            }
        }
    }

    // ---- reset barrier counters for graph replay ----
    __syncthreads();
    if (tid == 0) {
        __threadfence();
        unsigned v = atomicAdd(&g_done, 1u);
        if (v == CSR_GRID - 1) {
            g_bar = 0;
            g_done = 0;
            __threadfence();
        }
    }
}

// ---------------- mean aggregation: fp16 gathers, HADD2 tree, pre-scaled offsets ----------
// SSEL: 0 = g_xh, 1 = g_hah, 2 = g_hbh. Output: g_aggh (width C).
// g_src holds source_node*32: for C=128 it's the uint2 row offset, for C=64 the word offset.
template <int C, int SSEL>
__global__ void k_agg() {
    const __half* feat = (SSEL == 0) ? g_xh : (SSEL == 1) ? g_hah : g_hbh;
    int w    = (blockIdx.x * blockDim.x + threadIdx.x) >> 5;
    int lane = threadIdx.x & 31;
    if (w >= N_NODES) return;
    int beg = g_rowptr[w], end = g_rowptr[w + 1];
    if (C == 128) {
        const uint2* f = (const uint2*)feat;
        float a0 = 0.f, a1 = 0.f, a2 = 0.f, a3 = 0.f;
        int e = beg;
        for (; e + 3 < end; e += 4) {
            int o0 = g_src[e]     + lane;
            int o1 = g_src[e + 1] + lane;
            int o2 = g_src[e + 2] + lane;
            int o3 = g_src[e + 3] + lane;
            uint2 r0 = f[o0];
            uint2 r1 = f[o1];
            uint2 r2 = f[o2];
            uint2 r3 = f[o3];
            __half2 lo = __hadd2(__hadd2(*(__half2*)&r0.x, *(__half2*)&r1.x),
                                 __hadd2(*(__half2*)&r2.x, *(__half2*)&r3.x));
            __half2 hi = __hadd2(__hadd2(*(__half2*)&r0.y, *(__half2*)&r1.y),
                                 __hadd2(*(__half2*)&r2.y, *(__half2*)&r3.y));
            float2 pl = __half22float2(lo);
            float2 ph = __half22float2(hi);
            a0 += pl.x; a1 += pl.y; a2 += ph.x; a3 += ph.y;
        }
        for (; e < end; e++) {
            uint2 r0 = f[g_src[e] + lane];
            float2 p0 = __half22float2(*(__half2*)&r0.x);
            float2 p1 = __half22float2(*(__half2*)&r0.y);
            a0 += p0.x; a1 += p0.y; a2 += p1.x; a3 += p1.y;
        }
        float iv = g_invdeg[w];
        size_t base = (size_t)w * 128 + lane * 4;
        *(__half2*)&g_aggh[base]     = __floats2half2_rn(a0 * iv, a1 * iv);
        *(__half2*)&g_aggh[base + 2] = __floats2half2_rn(a2 * iv, a3 * iv);
    } else { // C == 64
        const unsigned* f = (const unsigned*)feat;
        float a0 = 0.f, a1 = 0.f;
        int e = beg;
        for (; e + 3 < end; e += 4) {
            unsigned r0 = f[g_src[e]     + lane];
            unsigned r1 = f[g_src[e + 1] + lane];
            unsigned r2 = f[g_src[e + 2] + lane];
            unsigned r3 = f[g_src[e + 3] + lane];
            __half2 s = __hadd2(__hadd2(*(__half2*)&r0, *(__half2*)&r1),
                                __hadd2(*(__half2*)&r2, *(__half2*)&r3));
            float2 p = __half22float2(s);
            a0 += p.x; a1 += p.y;
        }
        for (; e < end; e++) {
            unsigned r = f[g_src[e] + lane];
            float2 p = __half22float2(*(__half2*)&r);
            a0 += p.x; a1 += p.y;
        }
        float iv = g_invdeg[w];
        *(__half2*)&g_aggh[(size_t)w * 64 + lane * 2] = __floats2half2_rn(a0 * iv, a1 * iv);
    }
}

// ---------------- tensor-core SAGE layer (2 K-segments, pure fp16 operands) ----------------
// rnd 0: agg_hi @ Wl ; rnd 1: x_hi @ Wr.  fp32 accumulate, bias/relu/log_softmax epilogue.
// 2 blocks/SM: overlap staging of one block with MMA/epilogue of the other.
template <int CIN, int COUT, bool RELU, bool LSM, int XSEL, int OSEL, int WBASE>
__launch_bounds__(256, 2)
__global__ void k_mma(const float* __restrict__ bl, float* __restrict__ dout) {
    constexpr int PPS = CIN / 64;
    constexpr int CC  = COUT * CIN;
    constexpr int RT  = (COUT == 128) ? 2 : 1;

    extern __shared__ uint4 smemU4[];
    uint4* As0U4 = smemU4;
    uint4* Bs0U4 = As0U4 + 128 * 9;

    const __half* xh = (XSEL == 0) ? g_xh : (XSEL == 1) ? g_hah : g_hbh;

    const int tid = threadIdx.x, warp = tid >> 5, lane = tid & 31;
    const int g = lane >> 2, t = lane & 3;
    const int nb = blockIdx.x * 128;
    const int rowbase = (COUT == 128) ? (warp >> 1) * 32 : warp * 16;
    const int colbase = (COUT == 128) ? (warp & 1) * 64 : 0;

    float acc[RT][8][4];
    #pragma unroll
    for (int rt = 0; rt < RT; rt++)
        #pragma unroll
        for (int f = 0; f < 8; f++)
            #pragma unroll
            for (int j = 0; j < 4; j++) acc[rt][f][j] = 0.f;

    auto domma = [&](const unsigned* AW, const unsigned* BW) {
        #pragma unroll
        for (int kc = 0; kc < 4; kc++) {
            unsigned a[RT][4];
            #pragma unroll
            for (int rt = 0; rt < RT; rt++) {
                int r0 = rowbase + rt * 16 + g;
                a[rt][0] = AW[r0 * 36 + kc * 8 + t];
                a[rt][1] = AW[(r0 + 8) * 36 + kc * 8 + t];
                a[rt][2] = AW[r0 * 36 + kc * 8 + t + 4];
                a[rt][3] = AW[(r0 + 8) * 36 + kc * 8 + t + 4];
            }
            unsigned b[8][2];
            #pragma unroll
            for (int f = 0; f < 8; f++) {
                int br = colbase + f * 8 + g;
                b[f][0] = BW[br * 36 + kc * 8 + t];
                b[f][1] = BW[br * 36 + kc * 8 + t + 4];
            }
            #pragma unroll
            for (int rt = 0; rt < RT; rt++)
                #pragma unroll
                for (int f = 0; f < 8; f++)
                    mma16816(acc[rt][f], a[rt], b[f]);
        }
    };

    #pragma unroll
    for (int off4 = 0; off4 < PPS; off4++) {
        const int off = off4 * 64;
        #pragma unroll
        for (int rnd = 0; rnd < 2; rnd++) {
            const __half* A0 = (rnd == 0) ? g_aggh : xh;
            const int b0 = WBASE + ((rnd == 0) ? 0 : CC);   // Wl / Wr
            __syncthreads();
            #pragma unroll
            for (int it = 0; it < 4; it++) {
                int idx = tid + it * 256;
                int row = idx >> 3, q = idx & 7;
                int n = nb + row; if (n >= N_NODES) n = N_NODES - 1;
                As0U4[row * 9 + q] = ((const uint4*)A0)[(size_t)n * (CIN / 8) + off / 8 + q];
            }
            #pragma unroll
            for (int it = 0; it < COUT / 32; it++) {
                int idx = tid + it * 256;
                int row = idx >> 3, q = idx & 7;
                Bs0U4[row * 9 + q] = ((const uint4*)g_w16)[(b0 + row * CIN + off) / 8 + q];
            }
            __syncthreads();
            domma((const unsigned*)As0U4, (const unsigned*)Bs0U4);
        }
    }

    // ---------------- epilogue ----------------
    if (!LSM) {
        __half* oh = (OSEL == 1) ? g_hah : g_hbh;
        #pragma unroll
        for (int rt = 0; rt < RT; rt++) {
            int n0 = nb + rowbase + rt * 16 + g;
            int n1 = n0 + 8;
            #pragma unroll
            for (int f = 0; f < 8; f++) {
                int col = colbase + f * 8 + 2 * t;
                float2 bb = *(const float2*)&bl[col];
                float v0 = acc[rt][f][0] + bb.x, v1 = acc[rt][f][1] + bb.y;
                float v2 = acc[rt][f][2] + bb.x, v3 = acc[rt][f][3] + bb.y;
                if (RELU) {
                    v0 = fmaxf(v0, 0.f); v1 = fmaxf(v1, 0.f);
                    v2 = fmaxf(v2, 0.f); v3 = fmaxf(v3, 0.f);
                }
                if (n0 < N_NODES)
                    *(__half2*)&oh[(size_t)n0 * COUT + col] = __floats2half2_rn(v0, v1);
                if (n1 < N_NODES)
                    *(__half2*)&oh[(size_t)n1 * COUT + col] = __floats2half2_rn(v2, v3);
            }
        }
    } else {
        float v0[8], v1[8], w0[8], w1[8];
        float mxA = -1e30f, mxB = -1e30f;
        #pragma unroll
        for (int f = 0; f < 8; f++) {
            int col = f * 8 + 2 * t;
            float2 bb = *(const float2*)&bl[col];
            v0[f] = acc[0][f][0] + bb.x; v1[f] = acc[0][f][1] + bb.y;
            w0[f] = acc[0][f][2] + bb.x; w1[f] = acc[0][f][3] + bb.y;
            mxA = fmaxf(mxA, fmaxf(v0[f], v1[f]));
            mxB = fmaxf(mxB, fmaxf(w0[f], w1[f]));
        }
        #pragma unroll
        for (int m = 1; m < 4; m <<= 1) {
            mxA = fmaxf(mxA, __shfl_xor_sync(0xffffffffu, mxA, m));
            mxB = fmaxf(mxB, __shfl_xor_sync(0xffffffffu, mxB, m));
        }
        float sA = 0.f, sB = 0.f;
        #pragma unroll
        for (int f = 0; f < 8; f++) {
            sA += expf(v0[f] - mxA) + expf(v1[f] - mxA);
            sB += expf(w0[f] - mxB) + expf(w1[f] - mxB);
        }
        #pragma unroll
        for (int m = 1; m < 4; m <<= 1) {
            sA += __shfl_xor_sync(0xffffffffu, sA, m);
            sB += __shfl_xor_sync(0xffffffffu, sB, m);
        }
        float lA = mxA + logf(sA), lB = mxB + logf(sB);
        int n0 = nb + rowbase + g;
        int n1 = n0 + 8;
        if (n0 < N_NODES) {
            #pragma unroll
            for (int f = 0; f < 8; f++)
                *(float2*)&dout[(size_t)n0 * 64 + f * 8 + 2 * t] =
                    make_float2(v0[f] - lA, v1[f] - lA);
        }
        if (n1 < N_NODES) {
            #pragma unroll
            for (int f = 0; f < 8; f++)
                *(float2*)&dout[(size_t)n1 * 64 + f * 8 + 2 * t] =
                    make_float2(w0[f] - lB, w1[f] - lB);
        }
    }
}

// ---------------- launch ----------------
extern "C" void kernel_launch(void* const* d_in, const int* in_sizes, int n_in,
                              void* d_out, int out_size) {
    (void)in_sizes; (void)n_in; (void)out_size;
    const float* x   = (const float*)d_in[0];
    const void*  ei  = d_in[1];
    const float* Wl1 = (const float*)d_in[2];
    const float* bl1 = (const float*)d_in[3];
    const float* Wr1 = (const float*)d_in[4];
    const float* Wl2 = (const float*)d_in[5];
    const float* bl2 = (const float*)d_in[6];
    const float* Wr2 = (const float*)d_in[7];
    const float* Wl3 = (const float*)d_in[8];
    const float* bl3 = (const float*)d_in[9];
    const float* Wr3 = (const float*)d_in[10];
    const float* Wl4 = (const float*)d_in[11];
    const float* bl4 = (const float*)d_in[12];
    const float* Wr4 = (const float*)d_in[13];
    float* out = (float*)d_out;

    const int SMEM = 2 * 128 * 9 * 16;   // 36864 B
    cudaFuncSetAttribute(k_mma<128,128,true ,false,0,1,0    >, cudaFuncAttributeMaxDynamicSharedMemorySize, SMEM);
    cudaFuncSetAttribute(k_mma<128,128,true ,false,1,2,32768>, cudaFuncAttributeMaxDynamicSharedMemorySize, SMEM);
    cudaFuncSetAttribute(k_mma<128,64 ,true ,false,2,1,65536>, cudaFuncAttributeMaxDynamicSharedMemorySize, SMEM);
    cudaFuncSetAttribute(k_mma<64 ,64 ,false,true ,1,0,81920>, cudaFuncAttributeMaxDynamicSharedMemorySize, SMEM);

    // single-kernel preprocessing + CSR build
    k_csr<<<CSR_GRID, 256>>>(ei, x, Wl1, Wr1, Wl2, Wr2, Wl3, Wr3, Wl4, Wr4);

    const int AGG_GRID = (N_NODES * 32 + 255) / 256;
    const int GM = (N_NODES + 127) / 128;

    // L1
    k_agg<128, 0><<<AGG_GRID, 256>>>();
    k_mma<128, 128, true, false, 0, 1, 0><<<GM, 256, SMEM>>>(bl1, nullptr);
    // L2
    k_agg<128, 1><<<AGG_GRID, 256>>>();
    k_mma<128, 128, true, false, 1, 2, 32768><<<GM, 256, SMEM>>>(bl2, nullptr);
    // L3
    k_agg<128, 2><<<AGG_GRID, 256>>>();
    k_mma<128, 64, true, false, 2, 1, 65536><<<GM, 256, SMEM>>>(bl3, nullptr);
    // L4
    k_agg<64, 1><<<AGG_GRID, 256>>>();
    k_mma<64, 64, false, true, 1, 0, 81920><<<GM, 256, SMEM>>>(bl4, out);
}